// round 12
// baseline (speedup 1.0000x reference)
#include <cuda_runtime.h>
#include <cuda_bf16.h>
#include <cuda_fp16.h>
#include <math.h>
#include <stdint.h>

#define HID 2048
#define TOK 4096
#define NH 16
#define HD 128
#define SEQ 2048
#define QBF 127.0f

__device__ int8_t g_w8[4][HID * HID];
__device__ float g_s[4];
__device__ float g_part[4 * 64];
__device__ int8_t g_x8[TOK * HID];
__device__ float g_xg[TOK];
__device__ float g_q[TOK * HID];
__device__ float g_k[TOK * HID];
__device__ float g_v[TOK * HID];
__device__ float g_ctx[TOK * HID];
__device__ int8_t g_c8[TOK * HID];
__device__ float g_cg[TOK];
__device__ float g_tc[SEQ * 64];
__device__ float g_ts[SEQ * 64];
__device__ uint32_t g_qh[TOK * HID / 2];
__device__ uint32_t g_ql[TOK * HID / 2];
__device__ uint32_t g_kh[TOK * HID / 2];
__device__ uint32_t g_kl[TOK * HID / 2];
__device__ uint32_t g_vth[TOK * HID / 2];
__device__ uint32_t g_vtl[TOK * HID / 2];

__device__ __forceinline__ uint32_t sptr(const void* p) {
    return (uint32_t)__cvta_generic_to_shared(p);
}

#define CP16(s, g) asm volatile("cp.async.ca.shared.global [%0], [%1], 16;\n" ::"r"(s), "l"(g))
#define CPC asm volatile("cp.async.commit_group;\n")
#define CPW(n) asm volatile("cp.async.wait_group %0;\n" ::"n"(n))
#define LDSM4(r0, r1, r2, r3, a)                                                        \
    asm volatile("ldmatrix.sync.aligned.m8n8.x4.shared.b16 {%0,%1,%2,%3}, [%4];\n"      \
                 : "=r"(r0), "=r"(r1), "=r"(r2), "=r"(r3) : "r"(a))
#define MMAI(d, a, b)                                                                   \
    asm volatile("mma.sync.aligned.m16n8k32.row.col.s32.s8.s8.s32 "                     \
                 "{%0,%1,%2,%3},{%4,%5,%6,%7},{%8,%9},{%0,%1,%2,%3};\n"                 \
                 : "+r"(d[0]), "+r"(d[1]), "+r"(d[2]), "+r"(d[3])                       \
                 : "r"(a[0]), "r"(a[1]), "r"(a[2]), "r"(a[3]), "r"(b[0]), "r"(b[1]))
#define MMAH(d, a0, a1, a2, a3, b0, b1)                                                 \
    asm volatile("mma.sync.aligned.m16n8k16.row.col.f32.f16.f16.f32 "                   \
                 "{%0,%1,%2,%3},{%4,%5,%6,%7},{%8,%9},{%0,%1,%2,%3};\n"                 \
                 : "+f"(d[0]), "+f"(d[1]), "+f"(d[2]), "+f"(d[3])                       \
                 : "r"(a0), "r"(a1), "r"(a2), "r"(a3), "r"(b0), "r"(b1))

__device__ __forceinline__ void h2split(float x, float y, uint32_t& hi, uint32_t& lo) {
    __half2 h = __floats2half2_rn(x, y);
    float2 hf = __half22float2(h);
    __half2 l = __floats2half2_rn(x - hf.x, y - hf.y);
    hi = *(uint32_t*)&h;
    lo = *(uint32_t*)&l;
}

__global__ __launch_bounds__(512) void k_tab() {
    int i = blockIdx.x * 512 + threadIdx.x;
    int s = i >> 6, dp = i & 63;
    float ff = (float)pow(10000.0, -(double)dp / 64.0);
    float angf = (float)s * ff;
    double ang = fmod((double)angf, 6.283185307179586476925287);
    g_tc[i] = (float)cos(ang);
    g_ts[i] = (float)sin(ang);
}

__global__ __launch_bounds__(256) void k_wabs_partial(const float* __restrict__ w0,
        const float* __restrict__ w1, const float* __restrict__ w2, const float* __restrict__ w3) {
    const float* w = (blockIdx.y == 0) ? w0 : (blockIdx.y == 1) ? w1 : (blockIdx.y == 2) ? w2 : w3;
    const float4* w4 = (const float4*)(w + (size_t)blockIdx.x * 65536);
    float s = 0.f;
    for (int i = threadIdx.x; i < 16384; i += 256) {
        float4 v = w4[i];
        s += fabsf(v.x) + fabsf(v.y) + fabsf(v.z) + fabsf(v.w);
    }
    __shared__ float red[256];
    red[threadIdx.x] = s;
    __syncthreads();
    for (int st = 128; st > 0; st >>= 1) {
        if (threadIdx.x < st) red[threadIdx.x] += red[threadIdx.x + st];
        __syncthreads();
    }
    if (threadIdx.x == 0) g_part[blockIdx.y * 64 + blockIdx.x] = red[0];
}

__global__ __launch_bounds__(64) void k_wabs_final() {
    __shared__ float red[64];
    red[threadIdx.x] = g_part[blockIdx.x * 64 + threadIdx.x];
    __syncthreads();
    for (int st = 32; st > 0; st >>= 1) {
        if (threadIdx.x < st) red[threadIdx.x] += red[threadIdx.x + st];
        __syncthreads();
    }
    if (threadIdx.x == 0) g_s[blockIdx.x] = red[0] / (float)(HID * HID) + 1e-5f;
}

__global__ __launch_bounds__(256) void k_quant_w(const float* __restrict__ w0,
        const float* __restrict__ w1, const float* __restrict__ w2, const float* __restrict__ w3) {
    int m = blockIdx.y;
    const float* w = (m == 0) ? w0 : (m == 1) ? w1 : (m == 2) ? w2 : w3;
    float s = g_s[m];
    int idx = (blockIdx.x * 256 + threadIdx.x) * 4;
    float4 v = *(const float4*)(w + idx);
    float qx = fminf(1.f, fmaxf(-1.f, rintf(v.x / s)));
    float qy = fminf(1.f, fmaxf(-1.f, rintf(v.y / s)));
    float qz = fminf(1.f, fmaxf(-1.f, rintf(v.z / s)));
    float qw = fminf(1.f, fmaxf(-1.f, rintf(v.w / s)));
    char4 pk = make_char4((char)(int)qx, (char)(int)qy, (char)(int)qz, (char)(int)qw);
    *(char4*)&g_w8[m][idx] = pk;
}

__global__ __launch_bounds__(256) void k_quant_act(const float* __restrict__ ext, int use_ctx) {
    int row = blockIdx.x;
    const float* src = use_ctx ? g_ctx : ext;
    int8_t* dst = use_ctx ? g_c8 : g_x8;
    float* gout = use_ctx ? g_cg : g_xg;
    const float4* xr = (const float4*)(src + (size_t)row * HID);
    float4 v0 = xr[threadIdx.x];
    float4 v1 = xr[threadIdx.x + 256];
    float mx = fmaxf(fmaxf(fabsf(v0.x), fabsf(v0.y)), fmaxf(fabsf(v0.z), fabsf(v0.w)));
    mx = fmaxf(mx, fmaxf(fmaxf(fabsf(v1.x), fabsf(v1.y)), fmaxf(fabsf(v1.z), fabsf(v1.w))));
    __shared__ float red[256];
    red[threadIdx.x] = mx;
    __syncthreads();
    for (int st = 128; st > 0; st >>= 1) {
        if (threadIdx.x < st) red[threadIdx.x] = fmaxf(red[threadIdx.x], red[threadIdx.x + st]);
        __syncthreads();
    }
    float g = red[0] + 1e-5f;
    if (threadIdx.x == 0) gout[row] = g;
    float t = QBF / g;
    int8_t* orow = dst + (size_t)row * HID;
    float4 vv[2] = {v0, v1};
    int offs[2] = {(int)threadIdx.x * 4, ((int)threadIdx.x + 256) * 4};
#pragma unroll
    for (int hh = 0; hh < 2; ++hh) {
        float a = fminf(QBF, fmaxf(-QBF, rintf(vv[hh].x * t)));
        float b = fminf(QBF, fmaxf(-QBF, rintf(vv[hh].y * t)));
        float c = fminf(QBF, fmaxf(-QBF, rintf(vv[hh].z * t)));
        float d = fminf(QBF, fmaxf(-QBF, rintf(vv[hh].w * t)));
        char4 pk = make_char4((char)(int)a, (char)(int)b, (char)(int)c, (char)(int)d);
        *(char4*)&orow[offs[hh]] = pk;
    }
}

// ---- INT8 MMA GEMM: 4-stage cp.async pipeline, one barrier/iter ----
// mat0 < 0: mat = blockIdx.z (fused QKV). mat0 == 3: o-proj.
#define GEMM_SMEM (8 * 10240)
__global__ __launch_bounds__(256) void k_gemm(int mat0, float* __restrict__ dout) {
    extern __shared__ int8_t gsm8[];
    int8_t* As = gsm8;            // [4][10240]
    int8_t* Bs = gsm8 + 40960;    // [4][10240]
    int mat = (mat0 < 0) ? (int)blockIdx.z : mat0;
    const int8_t* A = (mat == 3) ? g_c8 : g_x8;
    const float* gv = (mat == 3) ? g_cg : g_xg;
    const int8_t* W = g_w8[mat];
    float* C = (mat == 0) ? g_q : (mat == 1) ? g_k : (mat == 2) ? g_v : dout;
    int tid = threadIdx.x;
    int bm = blockIdx.y * 128, bn = blockIdx.x * 128;
    int warp = tid >> 5, lane = tid & 31;
    int wm = (warp >> 2) * 64, wn = (warp & 3) * 32;
    int acc[4][4][4];
#pragma unroll
    for (int i = 0; i < 4; i++)
#pragma unroll
        for (int j = 0; j < 4; j++)
#pragma unroll
            for (int r = 0; r < 4; r++) acc[i][j][r] = 0;
    const int8_t* Ab = A + (size_t)bm * HID;
    const int8_t* Wb = W + (size_t)bn * HID;
#define GLOAD(st, kt)                                                                   \
    for (int c = tid; c < 512; c += 256) {                                              \
        int rr = c >> 2, kc = (c & 3) << 4;                                             \
        CP16(sptr(As + (st) * 10240 + rr * 80 + kc), Ab + (size_t)rr * HID + (kt) * 64 + kc); \
        CP16(sptr(Bs + (st) * 10240 + rr * 80 + kc), Wb + (size_t)rr * HID + (kt) * 64 + kc); \
    }
    GLOAD(0, 0); CPC;
    GLOAD(1, 1); CPC;
    GLOAD(2, 2); CPC;
    for (int kt = 0; kt < 32; kt++) {
        if (kt < 30) { CPW(2); } else if (kt == 30) { CPW(1); } else { CPW(0); }
        __syncthreads();
        if (kt < 29) { GLOAD((kt + 3) & 3, kt + 3); CPC; }
        int8_t* Ast = As + (kt & 3) * 10240;
        int8_t* Bst = Bs + (kt & 3) * 10240;
#pragma unroll
        for (int ks = 0; ks < 2; ks++) {
            uint32_t a[4][4], b[4][2];
#pragma unroll
            for (int am = 0; am < 4; am++) {
                uint32_t ad = sptr(Ast + (wm + am * 16 + (lane & 15)) * 80 + ks * 32 + ((lane >> 4) << 4));
                LDSM4(a[am][0], a[am][1], a[am][2], a[am][3], ad);
            }
#pragma unroll
            for (int bp = 0; bp < 2; bp++) {
                int g = lane >> 3;
                int nr = wn + bp * 16 + (lane & 7) + ((g >> 1) << 3);
                int kc = ks * 32 + ((g & 1) << 4);
                uint32_t ad = sptr(Bst + nr * 80 + kc);
                uint32_t r0, r1, r2, r3;
                LDSM4(r0, r1, r2, r3, ad);
                b[2 * bp][0] = r0; b[2 * bp][1] = r1;
                b[2 * bp + 1][0] = r2; b[2 * bp + 1][1] = r3;
            }
#pragma unroll
            for (int am = 0; am < 4; am++)
#pragma unroll
                for (int bf = 0; bf < 4; bf++) MMAI(acc[am][bf], a[am], b[bf]);
        }
    }
    float sw = g_s[mat] * (1.0f / QBF);
#pragma unroll
    for (int am = 0; am < 4; am++) {
        int r0 = bm + wm + am * 16 + (lane >> 2);
        float s0 = gv[r0] * sw, s1 = gv[r0 + 8] * sw;
#pragma unroll
        for (int bf = 0; bf < 4; bf++) {
            int cc = bn + wn + bf * 8 + ((lane & 3) << 1);
            float* p0 = C + (size_t)r0 * HID + cc;
            p0[0] = (float)acc[am][bf][0] * s0;
            p0[1] = (float)acc[am][bf][1] * s0;
            float* p1 = p0 + (size_t)8 * HID;
            p1[0] = (float)acc[am][bf][2] * s1;
            p1[1] = (float)acc[am][bf][3] * s1;
        }
    }
}

// RoPE + split: emit packed half2 hi/lo Q,K directly
__global__ __launch_bounds__(256) void k_rope() {
    int tok = blockIdx.x;
    int s = tok & (SEQ - 1);
    size_t tb = (size_t)tok * HID;
    for (int i = threadIdx.x; i < HID / 2; i += 256) {
        int d0 = 2 * i;
        float qv[2], kv[2];
#pragma unroll
        for (int u = 0; u < 2; u++) {
            int d = d0 + u;
            int dl = d & 127, dp = dl & 63;
            int partner = (d & ~127) | ((dl + 64) & 127);
            float c = g_tc[s * 64 + dp];
            float sn = g_ts[s * 64 + dp];
            float sgn = (dl < 64) ? -sn : sn;
            qv[u] = g_q[tb + d] * c + g_q[tb + partner] * sgn;
            kv[u] = g_k[tb + d] * c + g_k[tb + partner] * sgn;
        }
        uint32_t hh, ll;
        h2split(qv[0], qv[1], hh, ll);
        g_qh[tok * (HID / 2) + i] = hh;
        g_ql[tok * (HID / 2) + i] = ll;
        h2split(kv[0], kv[1], hh, ll);
        g_kh[tok * (HID / 2) + i] = hh;
        g_kl[tok * (HID / 2) + i] = ll;
    }
}

// V transpose + split
__global__ __launch_bounds__(256) void k_vt() {
    __shared__ float t[32][33];
    int s0 = blockIdx.x * 32, d0 = blockIdx.y * 32;
    int h = blockIdx.z & (NH - 1), b = blockIdx.z >> 4;
    int tx = threadIdx.x, ty = threadIdx.y;
    int tl = ty * 32 + tx;
#pragma unroll
    for (int i = 0; i < 4; i++) {
        int s = s0 + ty + 8 * i;
        t[ty + 8 * i][tx] = g_v[((size_t)(b * SEQ + s)) * HID + h * HD + d0 + tx];
    }
    __syncthreads();
    for (int e = tl; e < 512; e += 256) {
        int dl = e >> 4, p = e & 15;
        uint32_t hh, ll;
        h2split(t[2 * p][dl], t[2 * p + 1][dl], hh, ll);
        size_t ob = ((size_t)((b * NH + h) * HD + d0 + dl)) * (SEQ / 2) + s0 / 2 + p;
        g_vth[ob] = hh;
        g_vtl[ob] = ll;
    }
}

// flash attention (unchanged, passing): pre-split operands, K single / V double buffer
#define QST2 68
#define KST2 68
#define VST2 36
#define PST2 36
#define ATTN_SMEM (53760 * 4)
__global__ __launch_bounds__(256) void k_attn() {
    extern __shared__ uint32_t smu[];
    uint32_t* Qh = smu;
    uint32_t* Ql = smu + 8704;
    uint32_t* Kh = smu + 17408;
    uint32_t* Kl = smu + 21760;
    uint32_t* Vst = smu + 26112;
    uint32_t* Ph = smu + 44544;
    uint32_t* Pl = smu + 49152;
    int h = blockIdx.x, b = blockIdx.y, q0 = blockIdx.z * 128;
    int tid = threadIdx.x, w = tid >> 5, lane = tid & 31;
    int gr = lane >> 2, gc = lane & 3;
    const float scale = 0.08838834764831845f;
    const int HW = HID / 2;
    for (int e = tid; e < 4096; e += 256) {
        int arr = e >> 11, r = (e & 2047) >> 4, c = e & 15;
        uint32_t* ds = arr ? Ql : Qh;
        const uint32_t* sr = (arr ? g_ql : g_qh) + (size_t)(b * SEQ + q0 + r) * HW + h * 64 + c * 4;
        CP16(sptr(&ds[r * QST2 + c * 4]), sr);
    }
    for (int e = tid; e < 2048; e += 256) {
        int arr = e >> 10, r = (e & 1023) >> 4, c = e & 15;
        uint32_t* ds = arr ? Kl : Kh;
        const uint32_t* sr = (arr ? g_kl : g_kh) + (size_t)(b * SEQ + r) * HW + h * 64 + c * 4;
        CP16(sptr(&ds[r * KST2 + c * 4]), sr);
    }
    size_t vtb = (size_t)((b * NH + h) * HD) * (SEQ / 2);
    for (int e = tid; e < 2048; e += 256) {
        int arr = e >> 10, r = (e & 1023) >> 3, c = e & 7;
        uint32_t* ds = Vst + arr * 4608;
        const uint32_t* sr = (arr ? g_vtl : g_vth) + vtb + (size_t)r * (SEQ / 2) + c * 4;
        CP16(sptr(&ds[r * VST2 + c * 4]), sr);
    }
    CPC;
    float o[16][4];
#pragma unroll
    for (int i = 0; i < 16; i++) { o[i][0] = o[i][1] = o[i][2] = o[i][3] = 0.f; }
    float m_lo = -1e30f, m_hi = -1e30f, l_lo = 0.f, l_hi = 0.f;
    int wr = w * 16;
    const int r_lo = wr + gr, r_hi = wr + gr + 8;
    for (int kt = 0; kt < SEQ / 64; kt++) {
        CPW(0);
        __syncthreads();
        float c[8][4];
#pragma unroll
        for (int j = 0; j < 8; j++) { c[j][0] = c[j][1] = c[j][2] = c[j][3] = 0.f; }
#pragma unroll
        for (int ks = 0; ks < 8; ks++) {
            int cb = ks * 8;
            uint32_t ah0 = Qh[r_lo * QST2 + cb + gc], ah1 = Qh[r_hi * QST2 + cb + gc];
            uint32_t ah2 = Qh[r_lo * QST2 + cb + gc + 4], ah3 = Qh[r_hi * QST2 + cb + gc + 4];
            uint32_t al0 = Ql[r_lo * QST2 + cb + gc], al1 = Ql[r_hi * QST2 + cb + gc];
            uint32_t al2 = Ql[r_lo * QST2 + cb + gc + 4], al3 = Ql[r_hi * QST2 + cb + gc + 4];
#pragma unroll
            for (int nb = 0; nb < 8; nb++) {
                uint32_t bh0 = Kh[(nb * 8 + gr) * KST2 + cb + gc];
                uint32_t bh1 = Kh[(nb * 8 + gr) * KST2 + cb + gc + 4];
                uint32_t bl0 = Kl[(nb * 8 + gr) * KST2 + cb + gc];
                uint32_t bl1 = Kl[(nb * 8 + gr) * KST2 + cb + gc + 4];
                MMAH(c[nb], ah0, ah1, ah2, ah3, bh0, bh1);
                MMAH(c[nb], ah0, ah1, ah2, ah3, bl0, bl1);
                MMAH(c[nb], al0, al1, al2, al3, bh0, bh1);
            }
        }
        float mx_lo = -1e30f, mx_hi = -1e30f;
#pragma unroll
        for (int j = 0; j < 8; j++) {
            mx_lo = fmaxf(mx_lo, fmaxf(c[j][0], c[j][1]));
            mx_hi = fmaxf(mx_hi, fmaxf(c[j][2], c[j][3]));
        }
        mx_lo = fmaxf(mx_lo, __shfl_xor_sync(0xffffffffu, mx_lo, 1));
        mx_lo = fmaxf(mx_lo, __shfl_xor_sync(0xffffffffu, mx_lo, 2));
        mx_hi = fmaxf(mx_hi, __shfl_xor_sync(0xffffffffu, mx_hi, 1));
        mx_hi = fmaxf(mx_hi, __shfl_xor_sync(0xffffffffu, mx_hi, 2));
        float mn_lo = fmaxf(m_lo, mx_lo * scale);
        float mn_hi = fmaxf(m_hi, mx_hi * scale);
        float ts_lo = 0.f, ts_hi = 0.f;
#pragma unroll
        for (int j = 0; j < 8; j++) {
            c[j][0] = __expf(fmaf(c[j][0], scale, -mn_lo));
            c[j][1] = __expf(fmaf(c[j][1], scale, -mn_lo));
            c[j][2] = __expf(fmaf(c[j][2], scale, -mn_hi));
            c[j][3] = __expf(fmaf(c[j][3], scale, -mn_hi));
            ts_lo += c[j][0] + c[j][1];
            ts_hi += c[j][2] + c[j][3];
        }
        ts_lo += __shfl_xor_sync(0xffffffffu, ts_lo, 1);
        ts_lo += __shfl_xor_sync(0xffffffffu, ts_lo, 2);
        ts_hi += __shfl_xor_sync(0xffffffffu, ts_hi, 1);
        ts_hi += __shfl_xor_sync(0xffffffffu, ts_hi, 2);
        float co_lo = __expf(m_lo - mn_lo), co_hi = __expf(m_hi - mn_hi);
        m_lo = mn_lo; m_hi = mn_hi;
        l_lo = l_lo * co_lo + ts_lo;
        l_hi = l_hi * co_hi + ts_hi;
#pragma unroll
        for (int j = 0; j < 16; j++) {
            o[j][0] *= co_lo; o[j][1] *= co_lo;
            o[j][2] *= co_hi; o[j][3] *= co_hi;
        }
#pragma unroll
        for (int j = 0; j < 8; j++) {
            uint32_t ph, pl;
            h2split(c[j][0], c[j][1], ph, pl);
            Ph[r_lo * PST2 + 4 * j + gc] = ph;
            Pl[r_lo * PST2 + 4 * j + gc] = pl;
            h2split(c[j][2], c[j][3], ph, pl);
            Ph[r_hi * PST2 + 4 * j + gc] = ph;
            Pl[r_hi * PST2 + 4 * j + gc] = pl;
        }
        __syncthreads();
        if (kt < SEQ / 64 - 1) {
            int nk = kt + 1;
            for (int e = tid; e < 2048; e += 256) {
                int arr = e >> 10, r = (e & 1023) >> 4, c2 = e & 15;
                uint32_t* ds = arr ? Kl : Kh;
                const uint32_t* sr = (arr ? g_kl : g_kh) + (size_t)(b * SEQ + nk * 64 + r) * HW + h * 64 + c2 * 4;
                CP16(sptr(&ds[r * KST2 + c2 * 4]), sr);
            }
            uint32_t* vdst = Vst + (nk & 1) * 9216;
            for (int e = tid; e < 2048; e += 256) {
                int arr = e >> 10, r = (e & 1023) >> 3, c2 = e & 7;
                uint32_t* ds = vdst + arr * 4608;
                const uint32_t* sr = (arr ? g_vtl : g_vth) + vtb + (size_t)r * (SEQ / 2) + nk * 32 + c2 * 4;
                CP16(sptr(&ds[r * VST2 + c2 * 4]), sr);
            }
            CPC;
        }
        uint32_t* Vh = Vst + (kt & 1) * 9216;
        uint32_t* Vl = Vh + 4608;
#pragma unroll
        for (int ks = 0; ks < 4; ks++) {
            int cb = ks * 8;
            uint32_t ah0 = Ph[r_lo * PST2 + cb + gc], ah1 = Ph[r_hi * PST2 + cb + gc];
            uint32_t ah2 = Ph[r_lo * PST2 + cb + gc + 4], ah3 = Ph[r_hi * PST2 + cb + gc + 4];
            uint32_t al0 = Pl[r_lo * PST2 + cb + gc], al1 = Pl[r_hi * PST2 + cb + gc];
            uint32_t al2 = Pl[r_lo * PST2 + cb + gc + 4], al3 = Pl[r_hi * PST2 + cb + gc + 4];
#pragma unroll
            for (int nb = 0; nb < 16; nb++) {
                uint32_t bh0 = Vh[(nb * 8 + gr) * VST2 + cb + gc];
                uint32_t bh1 = Vh[(nb * 8 + gr) * VST2 + cb + gc + 4];
                uint32_t bl0 = Vl[(nb * 8 + gr) * VST2 + cb + gc];
                uint32_t bl1 = Vl[(nb * 8 + gr) * VST2 + cb + gc + 4];
                MMAH(o[nb], ah0, ah1, ah2, ah3, bh0, bh1);
                MMAH(o[nb], ah0, ah1, ah2, ah3, bl0, bl1);
                MMAH(o[nb], al0, al1, al2, al3, bh0, bh1);
            }
        }
    }
    float inv_lo = 1.f / l_lo, inv_hi = 1.f / l_hi;
    float* d_lo = g_ctx + ((size_t)(b * SEQ + q0 + r_lo)) * HID + h * HD;
    float* d_hi = g_ctx + ((size_t)(b * SEQ + q0 + r_hi)) * HID + h * HD;
#pragma unroll
    for (int nb = 0; nb < 16; nb++) {
        *(float2*)&d_lo[nb * 8 + 2 * gc] = make_float2(o[nb][0] * inv_lo, o[nb][1] * inv_lo);
        *(float2*)&d_hi[nb * 8 + 2 * gc] = make_float2(o[nb][2] * inv_hi, o[nb][3] * inv_hi);
    }
}

extern "C" void kernel_launch(void* const* d_in, const int* in_sizes, int n_in,
                              void* d_out, int out_size) {
    const float* x = (const float*)d_in[0];
    const float* wq = (const float*)d_in[1];
    const float* wk = (const float*)d_in[2];
    const float* wv = (const float*)d_in[3];
    const float* wo = (const float*)d_in[4];
    float* out = (float*)d_out;
    cudaFuncSetAttribute(k_attn, cudaFuncAttributeMaxDynamicSharedMemorySize, ATTN_SMEM);
    cudaFuncSetAttribute(k_gemm, cudaFuncAttributeMaxDynamicSharedMemorySize, GEMM_SMEM);
    k_tab<<<256, 512>>>();
    k_wabs_partial<<<dim3(64, 4), 256>>>(wq, wk, wv, wo);
    k_wabs_final<<<4, 64>>>();
    k_quant_w<<<dim3(HID * HID / 1024, 4), 256>>>(wq, wk, wv, wo);
    k_quant_act<<<TOK, 256>>>(x, 0);
    k_gemm<<<dim3(16, 32, 3), 256, GEMM_SMEM>>>(-1, out);
    k_rope<<<TOK, 256>>>();
    k_vt<<<dim3(SEQ / 32, HD / 32, NH * 2), dim3(32, 8)>>>();
    k_attn<<<dim3(NH, 2, SEQ / 128), 256, ATTN_SMEM>>>();
    k_quant_act<<<TOK, 256>>>(nullptr, 1);
    k_gemm<<<dim3(16, 32), 256, GEMM_SMEM>>>(3, out);
}

// round 13
// speedup vs baseline: 1.0852x; 1.0852x over previous
#include <cuda_runtime.h>
#include <cuda_bf16.h>
#include <cuda_fp16.h>
#include <math.h>
#include <stdint.h>

#define HID 2048
#define TOK 4096
#define NH 16
#define HD 128
#define SEQ 2048
#define QBF 127.0f

__device__ int8_t g_w8[4][HID * HID];
__device__ float g_s[4];
__device__ float g_part[4 * 64];
__device__ int8_t g_x8[TOK * HID];
__device__ float g_xg[TOK];
__device__ float g_q[TOK * HID];
__device__ float g_k[TOK * HID];
__device__ float g_v[TOK * HID];
__device__ float g_ctx[TOK * HID];
__device__ int8_t g_c8[TOK * HID];
__device__ float g_cg[TOK];
__device__ float g_tc[SEQ * 64];
__device__ float g_ts[SEQ * 64];
__device__ uint32_t g_qh[TOK * HID / 2];
__device__ uint32_t g_ql[TOK * HID / 2];
__device__ uint32_t g_kh[TOK * HID / 2];
__device__ uint32_t g_kl[TOK * HID / 2];
__device__ uint32_t g_vth[TOK * HID / 2];
__device__ uint32_t g_vtl[TOK * HID / 2];

__device__ __forceinline__ uint32_t sptr(const void* p) {
    return (uint32_t)__cvta_generic_to_shared(p);
}

#define CP16(s, g) asm volatile("cp.async.ca.shared.global [%0], [%1], 16;\n" ::"r"(s), "l"(g))
#define CPC asm volatile("cp.async.commit_group;\n")
#define CPW(n) asm volatile("cp.async.wait_group %0;\n" ::"n"(n))
#define LDSM4(r0, r1, r2, r3, a)                                                        \
    asm volatile("ldmatrix.sync.aligned.m8n8.x4.shared.b16 {%0,%1,%2,%3}, [%4];\n"      \
                 : "=r"(r0), "=r"(r1), "=r"(r2), "=r"(r3) : "r"(a))
#define MMAI(d, a, b)                                                                   \
    asm volatile("mma.sync.aligned.m16n8k32.row.col.s32.s8.s8.s32 "                     \
                 "{%0,%1,%2,%3},{%4,%5,%6,%7},{%8,%9},{%0,%1,%2,%3};\n"                 \
                 : "+r"(d[0]), "+r"(d[1]), "+r"(d[2]), "+r"(d[3])                       \
                 : "r"(a[0]), "r"(a[1]), "r"(a[2]), "r"(a[3]), "r"(b[0]), "r"(b[1]))
#define MMAH(d, a0, a1, a2, a3, b0, b1)                                                 \
    asm volatile("mma.sync.aligned.m16n8k16.row.col.f32.f16.f16.f32 "                   \
                 "{%0,%1,%2,%3},{%4,%5,%6,%7},{%8,%9},{%0,%1,%2,%3};\n"                 \
                 : "+f"(d[0]), "+f"(d[1]), "+f"(d[2]), "+f"(d[3])                       \
                 : "r"(a0), "r"(a1), "r"(a2), "r"(a3), "r"(b0), "r"(b1))

__device__ __forceinline__ void h2split(float x, float y, uint32_t& hi, uint32_t& lo) {
    __half2 h = __floats2half2_rn(x, y);
    float2 hf = __half22float2(h);
    __half2 l = __floats2half2_rn(x - hf.x, y - hf.y);
    hi = *(uint32_t*)&h;
    lo = *(uint32_t*)&l;
}

__global__ __launch_bounds__(512) void k_tab() {
    int i = blockIdx.x * 512 + threadIdx.x;
    int s = i >> 6, dp = i & 63;
    float ff = (float)pow(10000.0, -(double)dp / 64.0);
    float angf = (float)s * ff;
    double ang = fmod((double)angf, 6.283185307179586476925287);
    g_tc[i] = (float)cos(ang);
    g_ts[i] = (float)sin(ang);
}

__global__ __launch_bounds__(256) void k_wabs_partial(const float* __restrict__ w0,
        const float* __restrict__ w1, const float* __restrict__ w2, const float* __restrict__ w3) {
    const float* w = (blockIdx.y == 0) ? w0 : (blockIdx.y == 1) ? w1 : (blockIdx.y == 2) ? w2 : w3;
    const float4* w4 = (const float4*)(w + (size_t)blockIdx.x * 65536);
    float s = 0.f;
    for (int i = threadIdx.x; i < 16384; i += 256) {
        float4 v = w4[i];
        s += fabsf(v.x) + fabsf(v.y) + fabsf(v.z) + fabsf(v.w);
    }
    __shared__ float red[256];
    red[threadIdx.x] = s;
    __syncthreads();
    for (int st = 128; st > 0; st >>= 1) {
        if (threadIdx.x < st) red[threadIdx.x] += red[threadIdx.x + st];
        __syncthreads();
    }
    if (threadIdx.x == 0) g_part[blockIdx.y * 64 + blockIdx.x] = red[0];
}

__global__ __launch_bounds__(64) void k_wabs_final() {
    __shared__ float red[64];
    red[threadIdx.x] = g_part[blockIdx.x * 64 + threadIdx.x];
    __syncthreads();
    for (int st = 32; st > 0; st >>= 1) {
        if (threadIdx.x < st) red[threadIdx.x] += red[threadIdx.x + st];
        __syncthreads();
    }
    if (threadIdx.x == 0) g_s[blockIdx.x] = red[0] / (float)(HID * HID) + 1e-5f;
}

__global__ __launch_bounds__(256) void k_quant_w(const float* __restrict__ w0,
        const float* __restrict__ w1, const float* __restrict__ w2, const float* __restrict__ w3) {
    int m = blockIdx.y;
    const float* w = (m == 0) ? w0 : (m == 1) ? w1 : (m == 2) ? w2 : w3;
    float s = g_s[m];
    int idx = (blockIdx.x * 256 + threadIdx.x) * 4;
    float4 v = *(const float4*)(w + idx);
    float qx = fminf(1.f, fmaxf(-1.f, rintf(v.x / s)));
    float qy = fminf(1.f, fmaxf(-1.f, rintf(v.y / s)));
    float qz = fminf(1.f, fmaxf(-1.f, rintf(v.z / s)));
    float qw = fminf(1.f, fmaxf(-1.f, rintf(v.w / s)));
    char4 pk = make_char4((char)(int)qx, (char)(int)qy, (char)(int)qz, (char)(int)qw);
    *(char4*)&g_w8[m][idx] = pk;
}

__global__ __launch_bounds__(256) void k_quant_act(const float* __restrict__ ext, int use_ctx) {
    int row = blockIdx.x;
    const float* src = use_ctx ? g_ctx : ext;
    int8_t* dst = use_ctx ? g_c8 : g_x8;
    float* gout = use_ctx ? g_cg : g_xg;
    const float4* xr = (const float4*)(src + (size_t)row * HID);
    float4 v0 = xr[threadIdx.x];
    float4 v1 = xr[threadIdx.x + 256];
    float mx = fmaxf(fmaxf(fabsf(v0.x), fabsf(v0.y)), fmaxf(fabsf(v0.z), fabsf(v0.w)));
    mx = fmaxf(mx, fmaxf(fmaxf(fabsf(v1.x), fabsf(v1.y)), fmaxf(fabsf(v1.z), fabsf(v1.w))));
    __shared__ float red[256];
    red[threadIdx.x] = mx;
    __syncthreads();
    for (int st = 128; st > 0; st >>= 1) {
        if (threadIdx.x < st) red[threadIdx.x] = fmaxf(red[threadIdx.x], red[threadIdx.x + st]);
        __syncthreads();
    }
    float g = red[0] + 1e-5f;
    if (threadIdx.x == 0) gout[row] = g;
    float t = QBF / g;
    int8_t* orow = dst + (size_t)row * HID;
    float4 vv[2] = {v0, v1};
    int offs[2] = {(int)threadIdx.x * 4, ((int)threadIdx.x + 256) * 4};
#pragma unroll
    for (int hh = 0; hh < 2; ++hh) {
        float a = fminf(QBF, fmaxf(-QBF, rintf(vv[hh].x * t)));
        float b = fminf(QBF, fmaxf(-QBF, rintf(vv[hh].y * t)));
        float c = fminf(QBF, fmaxf(-QBF, rintf(vv[hh].z * t)));
        float d = fminf(QBF, fmaxf(-QBF, rintf(vv[hh].w * t)));
        char4 pk = make_char4((char)(int)a, (char)(int)b, (char)(int)c, (char)(int)d);
        *(char4*)&orow[offs[hh]] = pk;
    }
}

// ---- INT8 MMA GEMM (proven 2-stage; mat0<0 -> fused QKV via blockIdx.z) ----
__global__ __launch_bounds__(256) void k_gemm(int mat0, float* __restrict__ dout) {
    __shared__ int8_t As[2][128 * 80];
    __shared__ int8_t Bs[2][128 * 80];
    int mat = (mat0 < 0) ? (int)blockIdx.z : mat0;
    const int8_t* A = (mat == 3) ? g_c8 : g_x8;
    const float* gv = (mat == 3) ? g_cg : g_xg;
    const int8_t* W = g_w8[mat];
    float* C = (mat == 0) ? g_q : (mat == 1) ? g_k : (mat == 2) ? g_v : dout;
    int tid = threadIdx.x;
    int bm = blockIdx.y * 128, bn = blockIdx.x * 128;
    int warp = tid >> 5, lane = tid & 31;
    int wm = (warp >> 2) * 64, wn = (warp & 3) * 32;
    int acc[4][4][4];
#pragma unroll
    for (int i = 0; i < 4; i++)
#pragma unroll
        for (int j = 0; j < 4; j++)
#pragma unroll
            for (int r = 0; r < 4; r++) acc[i][j][r] = 0;
    const int8_t* Ab = A + (size_t)bm * HID;
    const int8_t* Wb = W + (size_t)bn * HID;
#define GLOAD(bf, k0)                                                              \
    for (int c = tid; c < 512; c += 256) {                                         \
        int rr = c >> 2, kc = (c & 3) << 4;                                        \
        CP16(sptr(&As[bf][rr * 80 + kc]), Ab + (size_t)rr * HID + (k0) + kc);      \
        CP16(sptr(&Bs[bf][rr * 80 + kc]), Wb + (size_t)rr * HID + (k0) + kc);      \
    }
    GLOAD(0, 0);
    CPC;
    for (int kt = 0; kt < 32; kt++) {
        int buf = kt & 1;
        if (kt < 31) {
            GLOAD(buf ^ 1, (kt + 1) * 64);
            CPC;
            CPW(1);
        } else {
            CPW(0);
        }
        __syncthreads();
#pragma unroll
        for (int ks = 0; ks < 2; ks++) {
            uint32_t a[4][4], b[4][2];
#pragma unroll
            for (int am = 0; am < 4; am++) {
                uint32_t ad = sptr(&As[buf][(wm + am * 16 + (lane & 15)) * 80 + ks * 32 + ((lane >> 4) << 4)]);
                LDSM4(a[am][0], a[am][1], a[am][2], a[am][3], ad);
            }
#pragma unroll
            for (int bp = 0; bp < 2; bp++) {
                int g = lane >> 3;
                int nr = wn + bp * 16 + (lane & 7) + ((g >> 1) << 3);
                int kc = ks * 32 + ((g & 1) << 4);
                uint32_t ad = sptr(&Bs[buf][nr * 80 + kc]);
                uint32_t r0, r1, r2, r3;
                LDSM4(r0, r1, r2, r3, ad);
                b[2 * bp][0] = r0; b[2 * bp][1] = r1;
                b[2 * bp + 1][0] = r2; b[2 * bp + 1][1] = r3;
            }
#pragma unroll
            for (int am = 0; am < 4; am++)
#pragma unroll
                for (int bf = 0; bf < 4; bf++) MMAI(acc[am][bf], a[am], b[bf]);
        }
        __syncthreads();
    }
    float sw = g_s[mat] * (1.0f / QBF);
#pragma unroll
    for (int am = 0; am < 4; am++) {
        int r0 = bm + wm + am * 16 + (lane >> 2);
        float s0 = gv[r0] * sw, s1 = gv[r0 + 8] * sw;
#pragma unroll
        for (int bf = 0; bf < 4; bf++) {
            int cc = bn + wn + bf * 8 + ((lane & 3) << 1);
            float* p0 = C + (size_t)r0 * HID + cc;
            p0[0] = (float)acc[am][bf][0] * s0;
            p0[1] = (float)acc[am][bf][1] * s0;
            float* p1 = p0 + (size_t)8 * HID;
            p1[0] = (float)acc[am][bf][2] * s1;
            p1[1] = (float)acc[am][bf][3] * s1;
        }
    }
}

// RoPE + split
__global__ __launch_bounds__(256) void k_rope() {
    int tok = blockIdx.x;
    int s = tok & (SEQ - 1);
    size_t tb = (size_t)tok * HID;
    for (int i = threadIdx.x; i < HID / 2; i += 256) {
        int d0 = 2 * i;
        float qv[2], kv[2];
#pragma unroll
        for (int u = 0; u < 2; u++) {
            int d = d0 + u;
            int dl = d & 127, dp = dl & 63;
            int partner = (d & ~127) | ((dl + 64) & 127);
            float c = g_tc[s * 64 + dp];
            float sn = g_ts[s * 64 + dp];
            float sgn = (dl < 64) ? -sn : sn;
            qv[u] = g_q[tb + d] * c + g_q[tb + partner] * sgn;
            kv[u] = g_k[tb + d] * c + g_k[tb + partner] * sgn;
        }
        uint32_t hh, ll;
        h2split(qv[0], qv[1], hh, ll);
        g_qh[tok * (HID / 2) + i] = hh;
        g_ql[tok * (HID / 2) + i] = ll;
        h2split(kv[0], kv[1], hh, ll);
        g_kh[tok * (HID / 2) + i] = hh;
        g_kl[tok * (HID / 2) + i] = ll;
    }
}

// V transpose + split
__global__ __launch_bounds__(256) void k_vt() {
    __shared__ float t[32][33];
    int s0 = blockIdx.x * 32, d0 = blockIdx.y * 32;
    int h = blockIdx.z & (NH - 1), b = blockIdx.z >> 4;
    int tx = threadIdx.x, ty = threadIdx.y;
    int tl = ty * 32 + tx;
#pragma unroll
    for (int i = 0; i < 4; i++) {
        int s = s0 + ty + 8 * i;
        t[ty + 8 * i][tx] = g_v[((size_t)(b * SEQ + s)) * HID + h * HD + d0 + tx];
    }
    __syncthreads();
    for (int e = tl; e < 512; e += 256) {
        int dl = e >> 4, p = e & 15;
        uint32_t hh, ll;
        h2split(t[2 * p][dl], t[2 * p + 1][dl], hh, ll);
        size_t ob = ((size_t)((b * NH + h) * HD + d0 + dl)) * (SEQ / 2) + s0 / 2 + p;
        g_vth[ob] = hh;
        g_vtl[ob] = ll;
    }
}

// flash attention: pre-split operands, ldmatrix.x4 fragment gathers
#define QST2 68
#define KST2 68
#define VST2 36
#define PST2 36
#define ATTN_SMEM (53760 * 4)
__global__ __launch_bounds__(256) void k_attn() {
    extern __shared__ uint32_t smu[];
    uint32_t* Qh = smu;
    uint32_t* Ql = smu + 8704;
    uint32_t* Kh = smu + 17408;
    uint32_t* Kl = smu + 21760;
    uint32_t* Vst = smu + 26112;
    uint32_t* Ph = smu + 44544;
    uint32_t* Pl = smu + 49152;
    int h = blockIdx.x, b = blockIdx.y, q0 = blockIdx.z * 128;
    int tid = threadIdx.x, w = tid >> 5, lane = tid & 31;
    int gr = lane >> 2, gc = lane & 3;
    const float scale = 0.08838834764831845f;
    const int HW = HID / 2;
    for (int e = tid; e < 4096; e += 256) {
        int arr = e >> 11, r = (e & 2047) >> 4, c = e & 15;
        uint32_t* ds = arr ? Ql : Qh;
        const uint32_t* sr = (arr ? g_ql : g_qh) + (size_t)(b * SEQ + q0 + r) * HW + h * 64 + c * 4;
        CP16(sptr(&ds[r * QST2 + c * 4]), sr);
    }
    for (int e = tid; e < 2048; e += 256) {
        int arr = e >> 10, r = (e & 1023) >> 4, c = e & 15;
        uint32_t* ds = arr ? Kl : Kh;
        const uint32_t* sr = (arr ? g_kl : g_kh) + (size_t)(b * SEQ + r) * HW + h * 64 + c * 4;
        CP16(sptr(&ds[r * KST2 + c * 4]), sr);
    }
    size_t vtb = (size_t)((b * NH + h) * HD) * (SEQ / 2);
    for (int e = tid; e < 2048; e += 256) {
        int arr = e >> 10, r = (e & 1023) >> 3, c = e & 7;
        uint32_t* ds = Vst + arr * 4608;
        const uint32_t* sr = (arr ? g_vtl : g_vth) + vtb + (size_t)r * (SEQ / 2) + c * 4;
        CP16(sptr(&ds[r * VST2 + c * 4]), sr);
    }
    CPC;
    float o[16][4];
#pragma unroll
    for (int i = 0; i < 16; i++) { o[i][0] = o[i][1] = o[i][2] = o[i][3] = 0.f; }
    float m_lo = -1e30f, m_hi = -1e30f, l_lo = 0.f, l_hi = 0.f;
    int wr = w * 16;
    const int r_lo = wr + gr, r_hi = wr + gr + 8;
    // ldmatrix address components (k_gemm-proven pattern)
    const int arow = wr + (lane & 15);
    const int acolb = (lane >> 4) << 2;          // u32 offset
    const int gg = lane >> 3;
    const int brow = (lane & 7) + ((gg >> 1) << 3);
    const int bcolb = (gg & 1) << 2;             // u32 offset
    for (int kt = 0; kt < SEQ / 64; kt++) {
        CPW(0);
        __syncthreads();
        float c[8][4];
#pragma unroll
        for (int j = 0; j < 8; j++) { c[j][0] = c[j][1] = c[j][2] = c[j][3] = 0.f; }
#pragma unroll
        for (int ks = 0; ks < 8; ks++) {
            int cb = ks * 8;
            uint32_t ah[4], al[4];
            uint32_t ad = sptr(&Qh[arow * QST2 + cb + acolb]);
            LDSM4(ah[0], ah[1], ah[2], ah[3], ad);
            ad = sptr(&Ql[arow * QST2 + cb + acolb]);
            LDSM4(al[0], al[1], al[2], al[3], ad);
#pragma unroll
            for (int nb2 = 0; nb2 < 4; nb2++) {
                uint32_t bh0, bh1, bh2, bh3, bl0, bl1, bl2, bl3;
                uint32_t bd = sptr(&Kh[(nb2 * 16 + brow) * KST2 + cb + bcolb]);
                LDSM4(bh0, bh1, bh2, bh3, bd);
                bd = sptr(&Kl[(nb2 * 16 + brow) * KST2 + cb + bcolb]);
                LDSM4(bl0, bl1, bl2, bl3, bd);
                MMAH(c[2 * nb2], ah[0], ah[1], ah[2], ah[3], bh0, bh1);
                MMAH(c[2 * nb2], ah[0], ah[1], ah[2], ah[3], bl0, bl1);
                MMAH(c[2 * nb2], al[0], al[1], al[2], al[3], bh0, bh1);
                MMAH(c[2 * nb2 + 1], ah[0], ah[1], ah[2], ah[3], bh2, bh3);
                MMAH(c[2 * nb2 + 1], ah[0], ah[1], ah[2], ah[3], bl2, bl3);
                MMAH(c[2 * nb2 + 1], al[0], al[1], al[2], al[3], bh2, bh3);
            }
        }
        float mx_lo = -1e30f, mx_hi = -1e30f;
#pragma unroll
        for (int j = 0; j < 8; j++) {
            mx_lo = fmaxf(mx_lo, fmaxf(c[j][0], c[j][1]));
            mx_hi = fmaxf(mx_hi, fmaxf(c[j][2], c[j][3]));
        }
        mx_lo = fmaxf(mx_lo, __shfl_xor_sync(0xffffffffu, mx_lo, 1));
        mx_lo = fmaxf(mx_lo, __shfl_xor_sync(0xffffffffu, mx_lo, 2));
        mx_hi = fmaxf(mx_hi, __shfl_xor_sync(0xffffffffu, mx_hi, 1));
        mx_hi = fmaxf(mx_hi, __shfl_xor_sync(0xffffffffu, mx_hi, 2));
        float mn_lo = fmaxf(m_lo, mx_lo * scale);
        float mn_hi = fmaxf(m_hi, mx_hi * scale);
        float ts_lo = 0.f, ts_hi = 0.f;
#pragma unroll
        for (int j = 0; j < 8; j++) {
            c[j][0] = __expf(fmaf(c[j][0], scale, -mn_lo));
            c[j][1] = __expf(fmaf(c[j][1], scale, -mn_lo));
            c[j][2] = __expf(fmaf(c[j][2], scale, -mn_hi));
            c[j][3] = __expf(fmaf(c[j][3], scale, -mn_hi));
            ts_lo += c[j][0] + c[j][1];
            ts_hi += c[j][2] + c[j][3];
        }
        ts_lo += __shfl_xor_sync(0xffffffffu, ts_lo, 1);
        ts_lo += __shfl_xor_sync(0xffffffffu, ts_lo, 2);
        ts_hi += __shfl_xor_sync(0xffffffffu, ts_hi, 1);
        ts_hi += __shfl_xor_sync(0xffffffffu, ts_hi, 2);
        float co_lo = __expf(m_lo - mn_lo), co_hi = __expf(m_hi - mn_hi);
        m_lo = mn_lo; m_hi = mn_hi;
        l_lo = l_lo * co_lo + ts_lo;
        l_hi = l_hi * co_hi + ts_hi;
#pragma unroll
        for (int j = 0; j < 16; j++) {
            o[j][0] *= co_lo; o[j][1] *= co_lo;
            o[j][2] *= co_hi; o[j][3] *= co_hi;
        }
#pragma unroll
        for (int j = 0; j < 8; j++) {
            uint32_t ph, pl;
            h2split(c[j][0], c[j][1], ph, pl);
            Ph[r_lo * PST2 + 4 * j + gc] = ph;
            Pl[r_lo * PST2 + 4 * j + gc] = pl;
            h2split(c[j][2], c[j][3], ph, pl);
            Ph[r_hi * PST2 + 4 * j + gc] = ph;
            Pl[r_hi * PST2 + 4 * j + gc] = pl;
        }
        __syncthreads();
        if (kt < SEQ / 64 - 1) {
            int nk = kt + 1;
            for (int e = tid; e < 2048; e += 256) {
                int arr = e >> 10, r = (e & 1023) >> 4, c2 = e & 15;
                uint32_t* ds = arr ? Kl : Kh;
                const uint32_t* sr = (arr ? g_kl : g_kh) + (size_t)(b * SEQ + nk * 64 + r) * HW + h * 64 + c2 * 4;
                CP16(sptr(&ds[r * KST2 + c2 * 4]), sr);
            }
            uint32_t* vdst = Vst + (nk & 1) * 9216;
            for (int e = tid; e < 2048; e += 256) {
                int arr = e >> 10, r = (e & 1023) >> 3, c2 = e & 7;
                uint32_t* ds = vdst + arr * 4608;
                const uint32_t* sr = (arr ? g_vtl : g_vth) + vtb + (size_t)r * (SEQ / 2) + nk * 32 + c2 * 4;
                CP16(sptr(&ds[r * VST2 + c2 * 4]), sr);
            }
            CPC;
        }
        uint32_t* Vh = Vst + (kt & 1) * 9216;
        uint32_t* Vl = Vh + 4608;
#pragma unroll
        for (int ks = 0; ks < 4; ks++) {
            int cb = ks * 8;
            uint32_t ah[4], al[4];
            uint32_t ad = sptr(&Ph[arow * PST2 + cb + acolb]);
            LDSM4(ah[0], ah[1], ah[2], ah[3], ad);
            ad = sptr(&Pl[arow * PST2 + cb + acolb]);
            LDSM4(al[0], al[1], al[2], al[3], ad);
#pragma unroll
            for (int nb2 = 0; nb2 < 8; nb2++) {
                uint32_t bh0, bh1, bh2, bh3, bl0, bl1, bl2, bl3;
                uint32_t bd = sptr(&Vh[(nb2 * 16 + brow) * VST2 + cb + bcolb]);
                LDSM4(bh0, bh1, bh2, bh3, bd);
                bd = sptr(&Vl[(nb2 * 16 + brow) * VST2 + cb + bcolb]);
                LDSM4(bl0, bl1, bl2, bl3, bd);
                MMAH(o[2 * nb2], ah[0], ah[1], ah[2], ah[3], bh0, bh1);
                MMAH(o[2 * nb2], ah[0], ah[1], ah[2], ah[3], bl0, bl1);
                MMAH(o[2 * nb2], al[0], al[1], al[2], al[3], bh0, bh1);
                MMAH(o[2 * nb2 + 1], ah[0], ah[1], ah[2], ah[3], bh2, bh3);
                MMAH(o[2 * nb2 + 1], ah[0], ah[1], ah[2], ah[3], bl2, bl3);
                MMAH(o[2 * nb2 + 1], al[0], al[1], al[2], al[3], bh2, bh3);
            }
        }
    }
    float inv_lo = 1.f / l_lo, inv_hi = 1.f / l_hi;
    float* d_lo = g_ctx + ((size_t)(b * SEQ + q0 + r_lo)) * HID + h * HD;
    float* d_hi = g_ctx + ((size_t)(b * SEQ + q0 + r_hi)) * HID + h * HD;
#pragma unroll
    for (int nb = 0; nb < 16; nb++) {
        *(float2*)&d_lo[nb * 8 + 2 * gc] = make_float2(o[nb][0] * inv_lo, o[nb][1] * inv_lo);
        *(float2*)&d_hi[nb * 8 + 2 * gc] = make_float2(o[nb][2] * inv_hi, o[nb][3] * inv_hi);
    }
}

extern "C" void kernel_launch(void* const* d_in, const int* in_sizes, int n_in,
                              void* d_out, int out_size) {
    const float* x = (const float*)d_in[0];
    const float* wq = (const float*)d_in[1];
    const float* wk = (const float*)d_in[2];
    const float* wv = (const float*)d_in[3];
    const float* wo = (const float*)d_in[4];
    float* out = (float*)d_out;
    cudaFuncSetAttribute(k_attn, cudaFuncAttributeMaxDynamicSharedMemorySize, ATTN_SMEM);
    k_tab<<<256, 512>>>();
    k_wabs_partial<<<dim3(64, 4), 256>>>(wq, wk, wv, wo);
    k_wabs_final<<<4, 64>>>();
    k_quant_w<<<dim3(HID * HID / 1024, 4), 256>>>(wq, wk, wv, wo);
    k_quant_act<<<TOK, 256>>>(x, 0);
    k_gemm<<<dim3(16, 32, 3), 256>>>(-1, out);
    k_rope<<<TOK, 256>>>();
    k_vt<<<dim3(SEQ / 32, HD / 32, NH * 2), dim3(32, 8)>>>();
    k_attn<<<dim3(NH, 2, SEQ / 128), 256, ATTN_SMEM>>>();
    k_quant_act<<<TOK, 256>>>(nullptr, 1);
    k_gemm<<<dim3(16, 32), 256>>>(3, out);
}

// round 16
// speedup vs baseline: 1.1017x; 1.0152x over previous
#include <cuda_runtime.h>
#include <cuda_bf16.h>
#include <cuda_fp16.h>
#include <math.h>
#include <stdint.h>

#define HID 2048
#define TOK 4096
#define NH 16
#define HD 128
#define SEQ 2048
#define QBF 127.0f

__device__ int8_t g_w8[4][HID * HID];
__device__ float g_s[4];
__device__ float g_part[4 * 64];
__device__ int8_t g_x8[TOK * HID];
__device__ float g_xg[TOK];
__device__ float g_ctx[TOK * HID];
__device__ int8_t g_c8[TOK * HID];
__device__ float g_cg[TOK];
__device__ float g_tc[SEQ * 64];
__device__ float g_ts[SEQ * 64];
__device__ uint32_t g_qh[TOK * HID / 2];
__device__ uint32_t g_ql[TOK * HID / 2];
__device__ uint32_t g_kh[TOK * HID / 2];
__device__ uint32_t g_kl[TOK * HID / 2];
__device__ uint32_t g_vth[TOK * HID / 2];
__device__ uint32_t g_vtl[TOK * HID / 2];

__device__ __forceinline__ uint32_t sptr(const void* p) {
    return (uint32_t)__cvta_generic_to_shared(p);
}

#define CP16(s, g) asm volatile("cp.async.ca.shared.global [%0], [%1], 16;\n" ::"r"(s), "l"(g))
#define CPC asm volatile("cp.async.commit_group;\n")
#define CPW(n) asm volatile("cp.async.wait_group %0;\n" ::"n"(n))
#define LDSM4(r0, r1, r2, r3, a)                                                        \
    asm volatile("ldmatrix.sync.aligned.m8n8.x4.shared.b16 {%0,%1,%2,%3}, [%4];\n"      \
                 : "=r"(r0), "=r"(r1), "=r"(r2), "=r"(r3) : "r"(a))
#define MMAI(d, a, b)                                                                   \
    asm volatile("mma.sync.aligned.m16n8k32.row.col.s32.s8.s8.s32 "                     \
                 "{%0,%1,%2,%3},{%4,%5,%6,%7},{%8,%9},{%0,%1,%2,%3};\n"                 \
                 : "+r"(d[0]), "+r"(d[1]), "+r"(d[2]), "+r"(d[3])                       \
                 : "r"(a[0]), "r"(a[1]), "r"(a[2]), "r"(a[3]), "r"(b[0]), "r"(b[1]))
#define MMAH(d, a0, a1, a2, a3, b0, b1)                                                 \
    asm volatile("mma.sync.aligned.m16n8k16.row.col.f32.f16.f16.f32 "                   \
                 "{%0,%1,%2,%3},{%4,%5,%6,%7},{%8,%9},{%0,%1,%2,%3};\n"                 \
                 : "+f"(d[0]), "+f"(d[1]), "+f"(d[2]), "+f"(d[3])                       \
                 : "r"(a0), "r"(a1), "r"(a2), "r"(a3), "r"(b0), "r"(b1))

__device__ __forceinline__ void h2split(float x, float y, uint32_t& hi, uint32_t& lo) {
    __half2 h = __floats2half2_rn(x, y);
    float2 hf = __half22float2(h);
    __half2 l = __floats2half2_rn(x - hf.x, y - hf.y);
    hi = *(uint32_t*)&h;
    lo = *(uint32_t*)&l;
}

__global__ __launch_bounds__(512) void k_tab() {
    int i = blockIdx.x * 512 + threadIdx.x;
    int s = i >> 6, dp = i & 63;
    float ff = (float)pow(10000.0, -(double)dp / 64.0);
    float angf = (float)s * ff;
    double ang = fmod((double)angf, 6.283185307179586476925287);
    g_tc[i] = (float)cos(ang);
    g_ts[i] = (float)sin(ang);
}

__global__ __launch_bounds__(256) void k_wabs_partial(const float* __restrict__ w0,
        const float* __restrict__ w1, const float* __restrict__ w2, const float* __restrict__ w3) {
    const float* w = (blockIdx.y == 0) ? w0 : (blockIdx.y == 1) ? w1 : (blockIdx.y == 2) ? w2 : w3;
    const float4* w4 = (const float4*)(w + (size_t)blockIdx.x * 65536);
    float s = 0.f;
    for (int i = threadIdx.x; i < 16384; i += 256) {
        float4 v = w4[i];
        s += fabsf(v.x) + fabsf(v.y) + fabsf(v.z) + fabsf(v.w);
    }
    __shared__ float red[256];
    red[threadIdx.x] = s;
    __syncthreads();
    for (int st = 128; st > 0; st >>= 1) {
        if (threadIdx.x < st) red[threadIdx.x] += red[threadIdx.x + st];
        __syncthreads();
    }
    if (threadIdx.x == 0) g_part[blockIdx.y * 64 + blockIdx.x] = red[0];
}

__global__ __launch_bounds__(64) void k_wabs_final() {
    __shared__ float red[64];
    red[threadIdx.x] = g_part[blockIdx.x * 64 + threadIdx.x];
    __syncthreads();
    for (int st = 32; st > 0; st >>= 1) {
        if (threadIdx.x < st) red[threadIdx.x] += red[threadIdx.x + st];
        __syncthreads();
    }
    if (threadIdx.x == 0) g_s[blockIdx.x] = red[0] / (float)(HID * HID) + 1e-5f;
}

__global__ __launch_bounds__(256) void k_quant_w(const float* __restrict__ w0,
        const float* __restrict__ w1, const float* __restrict__ w2, const float* __restrict__ w3) {
    int m = blockIdx.y;
    const float* w = (m == 0) ? w0 : (m == 1) ? w1 : (m == 2) ? w2 : w3;
    float s = g_s[m];
    int idx = (blockIdx.x * 256 + threadIdx.x) * 4;
    float4 v = *(const float4*)(w + idx);
    float qx = fminf(1.f, fmaxf(-1.f, rintf(v.x / s)));
    float qy = fminf(1.f, fmaxf(-1.f, rintf(v.y / s)));
    float qz = fminf(1.f, fmaxf(-1.f, rintf(v.z / s)));
    float qw = fminf(1.f, fmaxf(-1.f, rintf(v.w / s)));
    char4 pk = make_char4((char)(int)qx, (char)(int)qy, (char)(int)qz, (char)(int)qw);
    *(char4*)&g_w8[m][idx] = pk;
}

__global__ __launch_bounds__(256) void k_quant_act(const float* __restrict__ ext, int use_ctx) {
    int row = blockIdx.x;
    const float* src = use_ctx ? g_ctx : ext;
    int8_t* dst = use_ctx ? g_c8 : g_x8;
    float* gout = use_ctx ? g_cg : g_xg;
    const float4* xr = (const float4*)(src + (size_t)row * HID);
    float4 v0 = xr[threadIdx.x];
    float4 v1 = xr[threadIdx.x + 256];
    float mx = fmaxf(fmaxf(fabsf(v0.x), fabsf(v0.y)), fmaxf(fabsf(v0.z), fabsf(v0.w)));
    mx = fmaxf(mx, fmaxf(fmaxf(fabsf(v1.x), fabsf(v1.y)), fmaxf(fabsf(v1.z), fabsf(v1.w))));
    __shared__ float red[256];
    red[threadIdx.x] = mx;
    __syncthreads();
    for (int st = 128; st > 0; st >>= 1) {
        if (threadIdx.x < st) red[threadIdx.x] = fmaxf(red[threadIdx.x], red[threadIdx.x + st]);
        __syncthreads();
    }
    float g = red[0] + 1e-5f;
    if (threadIdx.x == 0) gout[row] = g;
    float t = QBF / g;
    int8_t* orow = dst + (size_t)row * HID;
    float4 vv[2] = {v0, v1};
    int offs[2] = {(int)threadIdx.x * 4, ((int)threadIdx.x + 256) * 4};
#pragma unroll
    for (int hh = 0; hh < 2; ++hh) {
        float a = fminf(QBF, fmaxf(-QBF, rintf(vv[hh].x * t)));
        float b = fminf(QBF, fmaxf(-QBF, rintf(vv[hh].y * t)));
        float c = fminf(QBF, fmaxf(-QBF, rintf(vv[hh].z * t)));
        float d = fminf(QBF, fmaxf(-QBF, rintf(vv[hh].w * t)));
        char4 pk = make_char4((char)(int)a, (char)(int)b, (char)(int)c, (char)(int)d);
        *(char4*)&orow[offs[hh]] = pk;
    }
}

// ---- INT8 MMA GEMM, fused epilogue: rope+split (q,k), transpose+split (v) ----
// mat0 < 0: mat = blockIdx.z (fused QKV). mat0 == 3: o-proj direct store.
#define GEMM_SMEM 66048
#define TST 129
__global__ __launch_bounds__(256) void k_gemm(int mat0, float* __restrict__ dout) {
    extern __shared__ int8_t gdyn[];
    int8_t* As = gdyn;            // [2][10240]
    int8_t* Bs = gdyn + 20480;    // [2][10240]
    int mat = (mat0 < 0) ? (int)blockIdx.z : mat0;
    const int8_t* A = (mat == 3) ? g_c8 : g_x8;
    const float* gv = (mat == 3) ? g_cg : g_xg;
    const int8_t* W = g_w8[mat];
    int tid = threadIdx.x;
    int bm = blockIdx.y * 128, bn = blockIdx.x * 128;
    int warp = tid >> 5, lane = tid & 31;
    int wm = (warp >> 2) * 64, wn = (warp & 3) * 32;
    int acc[4][4][4];
#pragma unroll
    for (int i = 0; i < 4; i++)
#pragma unroll
        for (int j = 0; j < 4; j++)
#pragma unroll
            for (int r = 0; r < 4; r++) acc[i][j][r] = 0;
    const int8_t* Ab = A + (size_t)bm * HID;
    const int8_t* Wb = W + (size_t)bn * HID;
#define GLOAD(bf, k0)                                                                      \
    for (int c = tid; c < 512; c += 256) {                                                 \
        int rr = c >> 2, kc = (c & 3) << 4;                                                \
        CP16(sptr(As + (bf) * 10240 + rr * 80 + kc), Ab + (size_t)rr * HID + (k0) + kc);   \
        CP16(sptr(Bs + (bf) * 10240 + rr * 80 + kc), Wb + (size_t)rr * HID + (k0) + kc);   \
    }
    GLOAD(0, 0);
    CPC;
    for (int kt = 0; kt < 32; kt++) {
        int buf = kt & 1;
        if (kt < 31) {
            GLOAD(buf ^ 1, (kt + 1) * 64);
            CPC;
            CPW(1);
        } else {
            CPW(0);
        }
        __syncthreads();
#pragma unroll
        for (int ks = 0; ks < 2; ks++) {
            uint32_t a[4][4], b[4][2];
#pragma unroll
            for (int am = 0; am < 4; am++) {
                uint32_t ad = sptr(As + buf * 10240 + (wm + am * 16 + (lane & 15)) * 80 + ks * 32 + ((lane >> 4) << 4));
                LDSM4(a[am][0], a[am][1], a[am][2], a[am][3], ad);
            }
#pragma unroll
            for (int bp = 0; bp < 2; bp++) {
                int g = lane >> 3;
                int nr = wn + bp * 16 + (lane & 7) + ((g >> 1) << 3);
                int kc = ks * 32 + ((g & 1) << 4);
                uint32_t ad = sptr(Bs + buf * 10240 + nr * 80 + kc);
                uint32_t r0, r1, r2, r3;
                LDSM4(r0, r1, r2, r3, ad);
                b[2 * bp][0] = r0; b[2 * bp][1] = r1;
                b[2 * bp + 1][0] = r2; b[2 * bp + 1][1] = r3;
            }
#pragma unroll
            for (int am = 0; am < 4; am++)
#pragma unroll
                for (int bf = 0; bf < 4; bf++) MMAI(acc[am][bf], a[am], b[bf]);
        }
        __syncthreads();
    }
    float sw = g_s[mat] * (1.0f / QBF);
    if (mat == 3) {
#pragma unroll
        for (int am = 0; am < 4; am++) {
            int r0 = bm + wm + am * 16 + (lane >> 2);
            float s0 = gv[r0] * sw, s1 = gv[r0 + 8] * sw;
#pragma unroll
            for (int bf = 0; bf < 4; bf++) {
                int cc = bn + wn + bf * 8 + ((lane & 3) << 1);
                float* p0 = dout + (size_t)r0 * HID + cc;
                p0[0] = (float)acc[am][bf][0] * s0;
                p0[1] = (float)acc[am][bf][1] * s0;
                float* p1 = p0 + (size_t)8 * HID;
                p1[0] = (float)acc[am][bf][2] * s1;
                p1[1] = (float)acc[am][bf][3] * s1;
            }
        }
        return;
    }
    // stage scaled fp32 tile in smem (stride TST)
    float* T = (float*)gdyn;
#pragma unroll
    for (int am = 0; am < 4; am++) {
        int rl = wm + am * 16 + (lane >> 2);
        float s0 = gv[bm + rl] * sw, s1 = gv[bm + rl + 8] * sw;
#pragma unroll
        for (int bf = 0; bf < 4; bf++) {
            int cc = wn + bf * 8 + ((lane & 3) << 1);
            T[rl * TST + cc] = (float)acc[am][bf][0] * s0;
            T[rl * TST + cc + 1] = (float)acc[am][bf][1] * s0;
            T[(rl + 8) * TST + cc] = (float)acc[am][bf][2] * s1;
            T[(rl + 8) * TST + cc + 1] = (float)acc[am][bf][3] * s1;
        }
    }
    __syncthreads();
    int hh = bn >> 7;
    if (mat <= 1) {
        uint32_t* Dh = (mat == 0) ? g_qh : g_kh;
        uint32_t* Dl = (mat == 0) ? g_ql : g_kl;
        for (int e = tid; e < 8192; e += 256) {
            int r = e >> 6, i = e & 63;
            int tok = bm + r, s = tok & (SEQ - 1);
            float val[2];
#pragma unroll
            for (int u = 0; u < 2; u++) {
                int d = 2 * i + u;
                int dp = d & 63;
                int pr = (d + 64) & 127;
                float cs = g_tc[s * 64 + dp];
                float sn = g_ts[s * 64 + dp];
                float sgn = (d < 64) ? -sn : sn;
                val[u] = T[r * TST + d] * cs + T[r * TST + pr] * sgn;
            }
            uint32_t hv, lv;
            h2split(val[0], val[1], hv, lv);
            size_t idx = (size_t)tok * (HID / 2) + hh * 64 + i;
            Dh[idx] = hv;
            Dl[idx] = lv;
        }
    } else {
        int bb = bm >> 11;
        int s0tok = bm & (SEQ - 1);
        for (int e = tid; e < 8192; e += 256) {
            int d = e >> 6, p = e & 63;
            uint32_t hv, lv;
            h2split(T[(2 * p) * TST + d], T[(2 * p + 1) * TST + d], hv, lv);
            size_t ob = ((size_t)((bb * NH + hh) * HD + d)) * (SEQ / 2) + (s0tok >> 1) + p;
            g_vth[ob] = hv;
            g_vtl[ob] = lv;
        }
    }
}

// flash attention (unchanged, passing): pre-split operands, ldmatrix.x4 gathers
#define QST2 68
#define KST2 68
#define VST2 36
#define PST2 36
#define ATTN_SMEM (53760 * 4)
__global__ __launch_bounds__(256) void k_attn() {
    extern __shared__ uint32_t smu[];
    uint32_t* Qh = smu;
    uint32_t* Ql = smu + 8704;
    uint32_t* Kh = smu + 17408;
    uint32_t* Kl = smu + 21760;
    uint32_t* Vst = smu + 26112;
    uint32_t* Ph = smu + 44544;
    uint32_t* Pl = smu + 49152;
    int h = blockIdx.x, b = blockIdx.y, q0 = blockIdx.z * 128;
    int tid = threadIdx.x, w = tid >> 5, lane = tid & 31;
    int gr = lane >> 2, gc = lane & 3;
    const float scale = 0.08838834764831845f;
    const int HW = HID / 2;
    for (int e = tid; e < 4096; e += 256) {
        int arr = e >> 11, r = (e & 2047) >> 4, c = e & 15;
        uint32_t* ds = arr ? Ql : Qh;
        const uint32_t* sr = (arr ? g_ql : g_qh) + (size_t)(b * SEQ + q0 + r) * HW + h * 64 + c * 4;
        CP16(sptr(&ds[r * QST2 + c * 4]), sr);
    }
    for (int e = tid; e < 2048; e += 256) {
        int arr = e >> 10, r = (e & 1023) >> 4, c = e & 15;
        uint32_t* ds = arr ? Kl : Kh;
        const uint32_t* sr = (arr ? g_kl : g_kh) + (size_t)(b * SEQ + r) * HW + h * 64 + c * 4;
        CP16(sptr(&ds[r * KST2 + c * 4]), sr);
    }
    size_t vtb = (size_t)((b * NH + h) * HD) * (SEQ / 2);
    for (int e = tid; e < 2048; e += 256) {
        int arr = e >> 10, r = (e & 1023) >> 3, c = e & 7;
        uint32_t* ds = Vst + arr * 4608;
        const uint32_t* sr = (arr ? g_vtl : g_vth) + vtb + (size_t)r * (SEQ / 2) + c * 4;
        CP16(sptr(&ds[r * VST2 + c * 4]), sr);
    }
    CPC;
    float o[16][4];
#pragma unroll
    for (int i = 0; i < 16; i++) { o[i][0] = o[i][1] = o[i][2] = o[i][3] = 0.f; }
    float m_lo = -1e30f, m_hi = -1e30f, l_lo = 0.f, l_hi = 0.f;
    int wr = w * 16;
    const int r_lo = wr + gr, r_hi = wr + gr + 8;
    const int arow = wr + (lane & 15);
    const int acolb = (lane >> 4) << 2;
    const int gg = lane >> 3;
    const int brow = (lane & 7) + ((gg >> 1) << 3);
    const int bcolb = (gg & 1) << 2;
    for (int kt = 0; kt < SEQ / 64; kt++) {
        CPW(0);
        __syncthreads();
        float c[8][4];
#pragma unroll
        for (int j = 0; j < 8; j++) { c[j][0] = c[j][1] = c[j][2] = c[j][3] = 0.f; }
#pragma unroll
        for (int ks = 0; ks < 8; ks++) {
            int cb = ks * 8;
            uint32_t ah[4], al[4];
            uint32_t ad = sptr(&Qh[arow * QST2 + cb + acolb]);
            LDSM4(ah[0], ah[1], ah[2], ah[3], ad);
            ad = sptr(&Ql[arow * QST2 + cb + acolb]);
            LDSM4(al[0], al[1], al[2], al[3], ad);
#pragma unroll
            for (int nb2 = 0; nb2 < 4; nb2++) {
                uint32_t bh0, bh1, bh2, bh3, bl0, bl1, bl2, bl3;
                uint32_t bd = sptr(&Kh[(nb2 * 16 + brow) * KST2 + cb + bcolb]);
                LDSM4(bh0, bh1, bh2, bh3, bd);
                bd = sptr(&Kl[(nb2 * 16 + brow) * KST2 + cb + bcolb]);
                LDSM4(bl0, bl1, bl2, bl3, bd);
                MMAH(c[2 * nb2], ah[0], ah[1], ah[2], ah[3], bh0, bh1);
                MMAH(c[2 * nb2], ah[0], ah[1], ah[2], ah[3], bl0, bl1);
                MMAH(c[2 * nb2], al[0], al[1], al[2], al[3], bh0, bh1);
                MMAH(c[2 * nb2 + 1], ah[0], ah[1], ah[2], ah[3], bh2, bh3);
                MMAH(c[2 * nb2 + 1], ah[0], ah[1], ah[2], ah[3], bl2, bl3);
                MMAH(c[2 * nb2 + 1], al[0], al[1], al[2], al[3], bh2, bh3);
            }
        }
        float mx_lo = -1e30f, mx_hi = -1e30f;
#pragma unroll
        for (int j = 0; j < 8; j++) {
            mx_lo = fmaxf(mx_lo, fmaxf(c[j][0], c[j][1]));
            mx_hi = fmaxf(mx_hi, fmaxf(c[j][2], c[j][3]));
        }
        mx_lo = fmaxf(mx_lo, __shfl_xor_sync(0xffffffffu, mx_lo, 1));
        mx_lo = fmaxf(mx_lo, __shfl_xor_sync(0xffffffffu, mx_lo, 2));
        mx_hi = fmaxf(mx_hi, __shfl_xor_sync(0xffffffffu, mx_hi, 1));
        mx_hi = fmaxf(mx_hi, __shfl_xor_sync(0xffffffffu, mx_hi, 2));
        float mn_lo = fmaxf(m_lo, mx_lo * scale);
        float mn_hi = fmaxf(m_hi, mx_hi * scale);
        float ts_lo = 0.f, ts_hi = 0.f;
#pragma unroll
        for (int j = 0; j < 8; j++) {
            c[j][0] = __expf(fmaf(c[j][0], scale, -mn_lo));
            c[j][1] = __expf(fmaf(c[j][1], scale, -mn_lo));
            c[j][2] = __expf(fmaf(c[j][2], scale, -mn_hi));
            c[j][3] = __expf(fmaf(c[j][3], scale, -mn_hi));
            ts_lo += c[j][0] + c[j][1];
            ts_hi += c[j][2] + c[j][3];
        }
        ts_lo += __shfl_xor_sync(0xffffffffu, ts_lo, 1);
        ts_lo += __shfl_xor_sync(0xffffffffu, ts_lo, 2);
        ts_hi += __shfl_xor_sync(0xffffffffu, ts_hi, 1);
        ts_hi += __shfl_xor_sync(0xffffffffu, ts_hi, 2);
        float co_lo = __expf(m_lo - mn_lo), co_hi = __expf(m_hi - mn_hi);
        m_lo = mn_lo; m_hi = mn_hi;
        l_lo = l_lo * co_lo + ts_lo;
        l_hi = l_hi * co_hi + ts_hi;
#pragma unroll
        for (int j = 0; j < 16; j++) {
            o[j][0] *= co_lo; o[j][1] *= co_lo;
            o[j][2] *= co_hi; o[j][3] *= co_hi;
        }
#pragma unroll
        for (int j = 0; j < 8; j++) {
            uint32_t ph, pl;
            h2split(c[j][0], c[j][1], ph, pl);
            Ph[r_lo * PST2 + 4 * j + gc] = ph;
            Pl[r_lo * PST2 + 4 * j + gc] = pl;
            h2split(c[j][2], c[j][3], ph, pl);
            Ph[r_hi * PST2 + 4 * j + gc] = ph;
            Pl[r_hi * PST2 + 4 * j + gc] = pl;
        }
        __syncthreads();
        if (kt < SEQ / 64 - 1) {
            int nk = kt + 1;
            for (int e = tid; e < 2048; e += 256) {
                int arr = e >> 10, r = (e & 1023) >> 4, c2 = e & 15;
                uint32_t* ds = arr ? Kl : Kh;
                const uint32_t* sr = (arr ? g_kl : g_kh) + (size_t)(b * SEQ + nk * 64 + r) * HW + h * 64 + c2 * 4;
                CP16(sptr(&ds[r * KST2 + c2 * 4]), sr);
            }
            uint32_t* vdst = Vst + (nk & 1) * 9216;
            for (int e = tid; e < 2048; e += 256) {
                int arr = e >> 10, r = (e & 1023) >> 3, c2 = e & 7;
                uint32_t* ds = vdst + arr * 4608;
                const uint32_t* sr = (arr ? g_vtl : g_vth) + vtb + (size_t)r * (SEQ / 2) + nk * 32 + c2 * 4;
                CP16(sptr(&ds[r * VST2 + c2 * 4]), sr);
            }
            CPC;
        }
        uint32_t* Vh = Vst + (kt & 1) * 9216;
        uint32_t* Vl = Vh + 4608;
#pragma unroll
        for (int ks = 0; ks < 4; ks++) {
            int cb = ks * 8;
            uint32_t ah[4], al[4];
            uint32_t ad = sptr(&Ph[arow * PST2 + cb + acolb]);
            LDSM4(ah[0], ah[1], ah[2], ah[3], ad);
            ad = sptr(&Pl[arow * PST2 + cb + acolb]);
            LDSM4(al[0], al[1], al[2], al[3], ad);
#pragma unroll
            for (int nb2 = 0; nb2 < 8; nb2++) {
                uint32_t bh0, bh1, bh2, bh3, bl0, bl1, bl2, bl3;
                uint32_t bd = sptr(&Vh[(nb2 * 16 + brow) * VST2 + cb + bcolb]);
                LDSM4(bh0, bh1, bh2, bh3, bd);
                bd = sptr(&Vl[(nb2 * 16 + brow) * VST2 + cb + bcolb]);
                LDSM4(bl0, bl1, bl2, bl3, bd);
                MMAH(o[2 * nb2], ah[0], ah[1], ah[2], ah[3], bh0, bh1);
                MMAH(o[2 * nb2], ah[0], ah[1], ah[2], ah[3], bl0, bl1);
                MMAH(o[2 * nb2], al[0], al[1], al[2], al[3], bh0, bh1);
                MMAH(o[2 * nb2 + 1], ah[0], ah[1], ah[2], ah[3], bh2, bh3);
                MMAH(o[2 * nb2 + 1], ah[0], ah[1], ah[2], ah[3], bl2, bl3);
                MMAH(o[2 * nb2 + 1], al[0], al[1], al[2], al[3], bh2, bh3);
            }
        }
    }
    float inv_lo = 1.f / l_lo, inv_hi = 1.f / l_hi;
    float* d_lo = g_ctx + ((size_t)(b * SEQ + q0 + r_lo)) * HID + h * HD;
    float* d_hi = g_ctx + ((size_t)(b * SEQ + q0 + r_hi)) * HID + h * HD;
#pragma unroll
    for (int nb = 0; nb < 16; nb++) {
        *(float2*)&d_lo[nb * 8 + 2 * gc] = make_float2(o[nb][0] * inv_lo, o[nb][1] * inv_lo);
        *(float2*)&d_hi[nb * 8 + 2 * gc] = make_float2(o[nb][2] * inv_hi, o[nb][3] * inv_hi);
    }
}

extern "C" void kernel_launch(void* const* d_in, const int* in_sizes, int n_in,
                              void* d_out, int out_size) {
    const float* x = (const float*)d_in[0];
    const float* wq = (const float*)d_in[1];
    const float* wk = (const float*)d_in[2];
    const float* wv = (const float*)d_in[3];
    const float* wo = (const float*)d_in[4];
    float* out = (float*)d_out;
    cudaFuncSetAttribute(k_attn, cudaFuncAttributeMaxDynamicSharedMemorySize, ATTN_SMEM);
    cudaFuncSetAttribute(k_gemm, cudaFuncAttributeMaxDynamicSharedMemorySize, GEMM_SMEM);
    k_tab<<<256, 512>>>();
    k_wabs_partial<<<dim3(64, 4), 256>>>(wq, wk, wv, wo);
    k_wabs_final<<<4, 64>>>();
    k_quant_w<<<dim3(HID * HID / 1024, 4), 256>>>(wq, wk, wv, wo);
    k_quant_act<<<TOK, 256>>>(x, 0);
    k_gemm<<<dim3(16, 32, 3), 256, GEMM_SMEM>>>(-1, out);
    k_attn<<<dim3(NH, 2, SEQ / 128), 256, ATTN_SMEM>>>();
    k_quant_act<<<TOK, 256>>>(nullptr, 1);
    k_gemm<<<dim3(16, 32), 256, GEMM_SMEM>>>(3, out);
}

// round 17
// speedup vs baseline: 1.1763x; 1.0677x over previous
#include <cuda_runtime.h>
#include <cuda_bf16.h>
#include <cuda_fp16.h>
#include <math.h>
#include <stdint.h>

#define HID 2048
#define TOK 4096
#define NH 16
#define HD 128
#define SEQ 2048
#define QBF 127.0f

__device__ int8_t g_w8[4][HID * HID];
__device__ float g_s[4];
__device__ float g_part[4 * 64];
__device__ int8_t g_x8[TOK * HID];
__device__ float g_xg[TOK];
__device__ float g_ctx[TOK * HID];
__device__ int8_t g_c8[TOK * HID];
__device__ float g_cg[TOK];
__device__ float g_tc[SEQ * 64];
__device__ float g_ts[SEQ * 64];
__device__ uint32_t g_qh[TOK * HID / 2];
__device__ uint32_t g_ql[TOK * HID / 2];
__device__ uint32_t g_kh[TOK * HID / 2];
__device__ uint32_t g_kl[TOK * HID / 2];
__device__ uint32_t g_vth[TOK * HID / 2];
__device__ uint32_t g_vtl[TOK * HID / 2];

__device__ __forceinline__ uint32_t sptr(const void* p) {
    return (uint32_t)__cvta_generic_to_shared(p);
}

#define CP16(s, g) asm volatile("cp.async.ca.shared.global [%0], [%1], 16;\n" ::"r"(s), "l"(g))
#define CPC asm volatile("cp.async.commit_group;\n")
#define CPW(n) asm volatile("cp.async.wait_group %0;\n" ::"n"(n))
#define LDSM4(r0, r1, r2, r3, a)                                                        \
    asm volatile("ldmatrix.sync.aligned.m8n8.x4.shared.b16 {%0,%1,%2,%3}, [%4];\n"      \
                 : "=r"(r0), "=r"(r1), "=r"(r2), "=r"(r3) : "r"(a))
#define MMAI(d, a, b)                                                                   \
    asm volatile("mma.sync.aligned.m16n8k32.row.col.s32.s8.s8.s32 "                     \
                 "{%0,%1,%2,%3},{%4,%5,%6,%7},{%8,%9},{%0,%1,%2,%3};\n"                 \
                 : "+r"(d[0]), "+r"(d[1]), "+r"(d[2]), "+r"(d[3])                       \
                 : "r"(a[0]), "r"(a[1]), "r"(a[2]), "r"(a[3]), "r"(b[0]), "r"(b[1]))
#define MMAH(d, a0, a1, a2, a3, b0, b1)                                                 \
    asm volatile("mma.sync.aligned.m16n8k16.row.col.f32.f16.f16.f32 "                   \
                 "{%0,%1,%2,%3},{%4,%5,%6,%7},{%8,%9},{%0,%1,%2,%3};\n"                 \
                 : "+f"(d[0]), "+f"(d[1]), "+f"(d[2]), "+f"(d[3])                       \
                 : "r"(a0), "r"(a1), "r"(a2), "r"(a3), "r"(b0), "r"(b1))

__device__ __forceinline__ void h2split(float x, float y, uint32_t& hi, uint32_t& lo) {
    __half2 h = __floats2half2_rn(x, y);
    float2 hf = __half22float2(h);
    __half2 l = __floats2half2_rn(x - hf.x, y - hf.y);
    hi = *(uint32_t*)&h;
    lo = *(uint32_t*)&l;
}

__global__ __launch_bounds__(512) void k_tab() {
    int i = blockIdx.x * 512 + threadIdx.x;
    int s = i >> 6, dp = i & 63;
    float ff = (float)pow(10000.0, -(double)dp / 64.0);
    float angf = (float)s * ff;
    double ang = fmod((double)angf, 6.283185307179586476925287);
    g_tc[i] = (float)cos(ang);
    g_ts[i] = (float)sin(ang);
}

__global__ __launch_bounds__(256) void k_wabs_partial(const float* __restrict__ w0,
        const float* __restrict__ w1, const float* __restrict__ w2, const float* __restrict__ w3) {
    const float* w = (blockIdx.y == 0) ? w0 : (blockIdx.y == 1) ? w1 : (blockIdx.y == 2) ? w2 : w3;
    const float4* w4 = (const float4*)(w + (size_t)blockIdx.x * 65536);
    float s = 0.f;
    for (int i = threadIdx.x; i < 16384; i += 256) {
        float4 v = w4[i];
        s += fabsf(v.x) + fabsf(v.y) + fabsf(v.z) + fabsf(v.w);
    }
    __shared__ float red[256];
    red[threadIdx.x] = s;
    __syncthreads();
    for (int st = 128; st > 0; st >>= 1) {
        if (threadIdx.x < st) red[threadIdx.x] += red[threadIdx.x + st];
        __syncthreads();
    }
    if (threadIdx.x == 0) g_part[blockIdx.y * 64 + blockIdx.x] = red[0];
}

__global__ __launch_bounds__(64) void k_wabs_final() {
    __shared__ float red[64];
    red[threadIdx.x] = g_part[blockIdx.x * 64 + threadIdx.x];
    __syncthreads();
    for (int st = 32; st > 0; st >>= 1) {
        if (threadIdx.x < st) red[threadIdx.x] += red[threadIdx.x + st];
        __syncthreads();
    }
    if (threadIdx.x == 0) g_s[blockIdx.x] = red[0] / (float)(HID * HID) + 1e-5f;
}

__global__ __launch_bounds__(256) void k_quant_w(const float* __restrict__ w0,
        const float* __restrict__ w1, const float* __restrict__ w2, const float* __restrict__ w3) {
    int m = blockIdx.y;
    const float* w = (m == 0) ? w0 : (m == 1) ? w1 : (m == 2) ? w2 : w3;
    float s = g_s[m];
    int idx = (blockIdx.x * 256 + threadIdx.x) * 4;
    float4 v = *(const float4*)(w + idx);
    float qx = fminf(1.f, fmaxf(-1.f, rintf(v.x / s)));
    float qy = fminf(1.f, fmaxf(-1.f, rintf(v.y / s)));
    float qz = fminf(1.f, fmaxf(-1.f, rintf(v.z / s)));
    float qw = fminf(1.f, fmaxf(-1.f, rintf(v.w / s)));
    char4 pk = make_char4((char)(int)qx, (char)(int)qy, (char)(int)qz, (char)(int)qw);
    *(char4*)&g_w8[m][idx] = pk;
}

__global__ __launch_bounds__(256) void k_quant_act(const float* __restrict__ ext, int use_ctx) {
    int row = blockIdx.x;
    const float* src = use_ctx ? g_ctx : ext;
    int8_t* dst = use_ctx ? g_c8 : g_x8;
    float* gout = use_ctx ? g_cg : g_xg;
    const float4* xr = (const float4*)(src + (size_t)row * HID);
    float4 v0 = xr[threadIdx.x];
    float4 v1 = xr[threadIdx.x + 256];
    float mx = fmaxf(fmaxf(fabsf(v0.x), fabsf(v0.y)), fmaxf(fabsf(v0.z), fabsf(v0.w)));
    mx = fmaxf(mx, fmaxf(fmaxf(fabsf(v1.x), fabsf(v1.y)), fmaxf(fabsf(v1.z), fabsf(v1.w))));
    __shared__ float red[256];
    red[threadIdx.x] = mx;
    __syncthreads();
    for (int st = 128; st > 0; st >>= 1) {
        if (threadIdx.x < st) red[threadIdx.x] = fmaxf(red[threadIdx.x], red[threadIdx.x + st]);
        __syncthreads();
    }
    float g = red[0] + 1e-5f;
    if (threadIdx.x == 0) gout[row] = g;
    float t = QBF / g;
    int8_t* orow = dst + (size_t)row * HID;
    float4 vv[2] = {v0, v1};
    int offs[2] = {(int)threadIdx.x * 4, ((int)threadIdx.x + 256) * 4};
#pragma unroll
    for (int hh = 0; hh < 2; ++hh) {
        float a = fminf(QBF, fmaxf(-QBF, rintf(vv[hh].x * t)));
        float b = fminf(QBF, fmaxf(-QBF, rintf(vv[hh].y * t)));
        float c = fminf(QBF, fmaxf(-QBF, rintf(vv[hh].z * t)));
        float d = fminf(QBF, fmaxf(-QBF, rintf(vv[hh].w * t)));
        char4 pk = make_char4((char)(int)a, (char)(int)b, (char)(int)c, (char)(int)d);
        *(char4*)&orow[offs[hh]] = pk;
    }
}

// ---- INT8 MMA GEMM, fused epilogue (unchanged, passing) ----
#define GEMM_SMEM 66048
#define TST 129
__global__ __launch_bounds__(256) void k_gemm(int mat0, float* __restrict__ dout) {
    extern __shared__ int8_t gdyn[];
    int8_t* As = gdyn;
    int8_t* Bs = gdyn + 20480;
    int mat = (mat0 < 0) ? (int)blockIdx.z : mat0;
    const int8_t* A = (mat == 3) ? g_c8 : g_x8;
    const float* gv = (mat == 3) ? g_cg : g_xg;
    const int8_t* W = g_w8[mat];
    int tid = threadIdx.x;
    int bm = blockIdx.y * 128, bn = blockIdx.x * 128;
    int warp = tid >> 5, lane = tid & 31;
    int wm = (warp >> 2) * 64, wn = (warp & 3) * 32;
    int acc[4][4][4];
#pragma unroll
    for (int i = 0; i < 4; i++)
#pragma unroll
        for (int j = 0; j < 4; j++)
#pragma unroll
            for (int r = 0; r < 4; r++) acc[i][j][r] = 0;
    const int8_t* Ab = A + (size_t)bm * HID;
    const int8_t* Wb = W + (size_t)bn * HID;
#define GLOAD(bf, k0)                                                                      \
    for (int c = tid; c < 512; c += 256) {                                                 \
        int rr = c >> 2, kc = (c & 3) << 4;                                                \
        CP16(sptr(As + (bf) * 10240 + rr * 80 + kc), Ab + (size_t)rr * HID + (k0) + kc);   \
        CP16(sptr(Bs + (bf) * 10240 + rr * 80 + kc), Wb + (size_t)rr * HID + (k0) + kc);   \
    }
    GLOAD(0, 0);
    CPC;
    for (int kt = 0; kt < 32; kt++) {
        int buf = kt & 1;
        if (kt < 31) {
            GLOAD(buf ^ 1, (kt + 1) * 64);
            CPC;
            CPW(1);
        } else {
            CPW(0);
        }
        __syncthreads();
#pragma unroll
        for (int ks = 0; ks < 2; ks++) {
            uint32_t a[4][4], b[4][2];
#pragma unroll
            for (int am = 0; am < 4; am++) {
                uint32_t ad = sptr(As + buf * 10240 + (wm + am * 16 + (lane & 15)) * 80 + ks * 32 + ((lane >> 4) << 4));
                LDSM4(a[am][0], a[am][1], a[am][2], a[am][3], ad);
            }
#pragma unroll
            for (int bp = 0; bp < 2; bp++) {
                int g = lane >> 3;
                int nr = wn + bp * 16 + (lane & 7) + ((g >> 1) << 3);
                int kc = ks * 32 + ((g & 1) << 4);
                uint32_t ad = sptr(Bs + buf * 10240 + nr * 80 + kc);
                uint32_t r0, r1, r2, r3;
                LDSM4(r0, r1, r2, r3, ad);
                b[2 * bp][0] = r0; b[2 * bp][1] = r1;
                b[2 * bp + 1][0] = r2; b[2 * bp + 1][1] = r3;
            }
#pragma unroll
            for (int am = 0; am < 4; am++)
#pragma unroll
                for (int bf = 0; bf < 4; bf++) MMAI(acc[am][bf], a[am], b[bf]);
        }
        __syncthreads();
    }
    float sw = g_s[mat] * (1.0f / QBF);
    if (mat == 3) {
#pragma unroll
        for (int am = 0; am < 4; am++) {
            int r0 = bm + wm + am * 16 + (lane >> 2);
            float s0 = gv[r0] * sw, s1 = gv[r0 + 8] * sw;
#pragma unroll
            for (int bf = 0; bf < 4; bf++) {
                int cc = bn + wn + bf * 8 + ((lane & 3) << 1);
                float* p0 = dout + (size_t)r0 * HID + cc;
                p0[0] = (float)acc[am][bf][0] * s0;
                p0[1] = (float)acc[am][bf][1] * s0;
                float* p1 = p0 + (size_t)8 * HID;
                p1[0] = (float)acc[am][bf][2] * s1;
                p1[1] = (float)acc[am][bf][3] * s1;
            }
        }
        return;
    }
    float* T = (float*)gdyn;
#pragma unroll
    for (int am = 0; am < 4; am++) {
        int rl = wm + am * 16 + (lane >> 2);
        float s0 = gv[bm + rl] * sw, s1 = gv[bm + rl + 8] * sw;
#pragma unroll
        for (int bf = 0; bf < 4; bf++) {
            int cc = wn + bf * 8 + ((lane & 3) << 1);
            T[rl * TST + cc] = (float)acc[am][bf][0] * s0;
            T[rl * TST + cc + 1] = (float)acc[am][bf][1] * s0;
            T[(rl + 8) * TST + cc] = (float)acc[am][bf][2] * s1;
            T[(rl + 8) * TST + cc + 1] = (float)acc[am][bf][3] * s1;
        }
    }
    __syncthreads();
    int hh = bn >> 7;
    if (mat <= 1) {
        uint32_t* Dh = (mat == 0) ? g_qh : g_kh;
        uint32_t* Dl = (mat == 0) ? g_ql : g_kl;
        for (int e = tid; e < 8192; e += 256) {
            int r = e >> 6, i = e & 63;
            int tok = bm + r, s = tok & (SEQ - 1);
            float val[2];
#pragma unroll
            for (int u = 0; u < 2; u++) {
                int d = 2 * i + u;
                int dp = d & 63;
                int pr = (d + 64) & 127;
                float cs = g_tc[s * 64 + dp];
                float sn = g_ts[s * 64 + dp];
                float sgn = (d < 64) ? -sn : sn;
                val[u] = T[r * TST + d] * cs + T[r * TST + pr] * sgn;
            }
            uint32_t hv, lv;
            h2split(val[0], val[1], hv, lv);
            size_t idx = (size_t)tok * (HID / 2) + hh * 64 + i;
            Dh[idx] = hv;
            Dl[idx] = lv;
        }
    } else {
        int bb = bm >> 11;
        int s0tok = bm & (SEQ - 1);
        for (int e = tid; e < 8192; e += 256) {
            int d = e >> 6, p = e & 63;
            uint32_t hv, lv;
            h2split(T[(2 * p) * TST + d], T[(2 * p + 1) * TST + d], hv, lv);
            size_t ob = ((size_t)((bb * NH + hh) * HD + d)) * (SEQ / 2) + (s0tok >> 1) + p;
            g_vth[ob] = hv;
            g_vtl[ob] = lv;
        }
    }
}

// flash attention: Q fragments hoisted to registers; P fed to PV directly from
// C-fragments (no smem stash). K single-buffer, V double-buffer via cp.async.
#define QST2 68
#define KST2 68
#define VST2 36
#define ATTN_SMEM (44544 * 4)
__global__ __launch_bounds__(256) void k_attn() {
    extern __shared__ uint32_t smu[];
    uint32_t* Qh = smu;                 // 128*68
    uint32_t* Ql = smu + 8704;
    uint32_t* Kh = smu + 17408;         // 64*68
    uint32_t* Kl = smu + 21760;
    uint32_t* Vst = smu + 26112;        // 2 stages x (Vh 128*36 + Vl 128*36)
    int h = blockIdx.x, b = blockIdx.y, q0 = blockIdx.z * 128;
    int tid = threadIdx.x, w = tid >> 5, lane = tid & 31;
    int gr = lane >> 2, gc = lane & 3;
    const float scale = 0.08838834764831845f;
    const int HW = HID / 2;
    for (int e = tid; e < 4096; e += 256) {
        int arr = e >> 11, r = (e & 2047) >> 4, c = e & 15;
        uint32_t* ds = arr ? Ql : Qh;
        const uint32_t* sr = (arr ? g_ql : g_qh) + (size_t)(b * SEQ + q0 + r) * HW + h * 64 + c * 4;
        CP16(sptr(&ds[r * QST2 + c * 4]), sr);
    }
    for (int e = tid; e < 2048; e += 256) {
        int arr = e >> 10, r = (e & 1023) >> 4, c = e & 15;
        uint32_t* ds = arr ? Kl : Kh;
        const uint32_t* sr = (arr ? g_kl : g_kh) + (size_t)(b * SEQ + r) * HW + h * 64 + c * 4;
        CP16(sptr(&ds[r * KST2 + c * 4]), sr);
    }
    size_t vtb = (size_t)((b * NH + h) * HD) * (SEQ / 2);
    for (int e = tid; e < 2048; e += 256) {
        int arr = e >> 10, r = (e & 1023) >> 3, c = e & 7;
        uint32_t* ds = Vst + arr * 4608;
        const uint32_t* sr = (arr ? g_vtl : g_vth) + vtb + (size_t)r * (SEQ / 2) + c * 4;
        CP16(sptr(&ds[r * VST2 + c * 4]), sr);
    }
    CPC;
    float o[16][4];
#pragma unroll
    for (int i = 0; i < 16; i++) { o[i][0] = o[i][1] = o[i][2] = o[i][3] = 0.f; }
    float m_lo = -1e30f, m_hi = -1e30f, l_lo = 0.f, l_hi = 0.f;
    int wr = w * 16;
    const int r_lo = wr + gr, r_hi = wr + gr + 8;
    const int arow = wr + (lane & 15);
    const int acolb = (lane >> 4) << 2;
    const int gg = lane >> 3;
    const int brow = (lane & 7) + ((gg >> 1) << 3);
    const int bcolb = (gg & 1) << 2;
    // wait for prologue loads, hoist Q fragments into registers
    CPW(0);
    __syncthreads();
    uint32_t qfh[8][4], qfl[8][4];
#pragma unroll
    for (int ks = 0; ks < 8; ks++) {
        int cb = ks * 8;
        uint32_t ad = sptr(&Qh[arow * QST2 + cb + acolb]);
        LDSM4(qfh[ks][0], qfh[ks][1], qfh[ks][2], qfh[ks][3], ad);
        ad = sptr(&Ql[arow * QST2 + cb + acolb]);
        LDSM4(qfl[ks][0], qfl[ks][1], qfl[ks][2], qfl[ks][3], ad);
    }
    for (int kt = 0; kt < SEQ / 64; kt++) {
        if (kt > 0) {
            CPW(0);
            __syncthreads();
        }
        float c[8][4];
#pragma unroll
        for (int j = 0; j < 8; j++) { c[j][0] = c[j][1] = c[j][2] = c[j][3] = 0.f; }
#pragma unroll
        for (int ks = 0; ks < 8; ks++) {
            int cb = ks * 8;
#pragma unroll
            for (int nb2 = 0; nb2 < 4; nb2++) {
                uint32_t bh0, bh1, bh2, bh3, bl0, bl1, bl2, bl3;
                uint32_t bd = sptr(&Kh[(nb2 * 16 + brow) * KST2 + cb + bcolb]);
                LDSM4(bh0, bh1, bh2, bh3, bd);
                bd = sptr(&Kl[(nb2 * 16 + brow) * KST2 + cb + bcolb]);
                LDSM4(bl0, bl1, bl2, bl3, bd);
                MMAH(c[2 * nb2], qfh[ks][0], qfh[ks][1], qfh[ks][2], qfh[ks][3], bh0, bh1);
                MMAH(c[2 * nb2], qfh[ks][0], qfh[ks][1], qfh[ks][2], qfh[ks][3], bl0, bl1);
                MMAH(c[2 * nb2], qfl[ks][0], qfl[ks][1], qfl[ks][2], qfl[ks][3], bh0, bh1);
                MMAH(c[2 * nb2 + 1], qfh[ks][0], qfh[ks][1], qfh[ks][2], qfh[ks][3], bh2, bh3);
                MMAH(c[2 * nb2 + 1], qfh[ks][0], qfh[ks][1], qfh[ks][2], qfh[ks][3], bl2, bl3);
                MMAH(c[2 * nb2 + 1], qfl[ks][0], qfl[ks][1], qfl[ks][2], qfl[ks][3], bh2, bh3);
            }
        }
        float mx_lo = -1e30f, mx_hi = -1e30f;
#pragma unroll
        for (int j = 0; j < 8; j++) {
            mx_lo = fmaxf(mx_lo, fmaxf(c[j][0], c[j][1]));
            mx_hi = fmaxf(mx_hi, fmaxf(c[j][2], c[j][3]));
        }
        mx_lo = fmaxf(mx_lo, __shfl_xor_sync(0xffffffffu, mx_lo, 1));
        mx_lo = fmaxf(mx_lo, __shfl_xor_sync(0xffffffffu, mx_lo, 2));
        mx_hi = fmaxf(mx_hi, __shfl_xor_sync(0xffffffffu, mx_hi, 1));
        mx_hi = fmaxf(mx_hi, __shfl_xor_sync(0xffffffffu, mx_hi, 2));
        float mn_lo = fmaxf(m_lo, mx_lo * scale);
        float mn_hi = fmaxf(m_hi, mx_hi * scale);
        float ts_lo = 0.f, ts_hi = 0.f;
#pragma unroll
        for (int j = 0; j < 8; j++) {
            c[j][0] = __expf(fmaf(c[j][0], scale, -mn_lo));
            c[j][1] = __expf(fmaf(c[j][1], scale, -mn_lo));
            c[j][2] = __expf(fmaf(c[j][2], scale, -mn_hi));
            c[j][3] = __expf(fmaf(c[j][3], scale, -mn_hi));
            ts_lo += c[j][0] + c[j][1];
            ts_hi += c[j][2] + c[j][3];
        }
        ts_lo += __shfl_xor_sync(0xffffffffu, ts_lo, 1);
        ts_lo += __shfl_xor_sync(0xffffffffu, ts_lo, 2);
        ts_hi += __shfl_xor_sync(0xffffffffu, ts_hi, 1);
        ts_hi += __shfl_xor_sync(0xffffffffu, ts_hi, 2);
        float co_lo = __expf(m_lo - mn_lo), co_hi = __expf(m_hi - mn_hi);
        m_lo = mn_lo; m_hi = mn_hi;
        l_lo = l_lo * co_lo + ts_lo;
        l_hi = l_hi * co_hi + ts_hi;
#pragma unroll
        for (int j = 0; j < 16; j++) {
            o[j][0] *= co_lo; o[j][1] *= co_lo;
            o[j][2] *= co_hi; o[j][3] *= co_hi;
        }
        // all warps done reading K -> safe to overwrite with next tile
        __syncthreads();
        if (kt < SEQ / 64 - 1) {
            int nk = kt + 1;
            for (int e = tid; e < 2048; e += 256) {
                int arr = e >> 10, r = (e & 1023) >> 4, c2 = e & 15;
                uint32_t* ds = arr ? Kl : Kh;
                const uint32_t* sr = (arr ? g_kl : g_kh) + (size_t)(b * SEQ + nk * 64 + r) * HW + h * 64 + c2 * 4;
                CP16(sptr(&ds[r * KST2 + c2 * 4]), sr);
            }
            uint32_t* vdst = Vst + (nk & 1) * 9216;
            for (int e = tid; e < 2048; e += 256) {
                int arr = e >> 10, r = (e & 1023) >> 3, c2 = e & 7;
                uint32_t* ds = vdst + arr * 4608;
                const uint32_t* sr = (arr ? g_vtl : g_vth) + vtb + (size_t)r * (SEQ / 2) + nk * 32 + c2 * 4;
                CP16(sptr(&ds[r * VST2 + c2 * 4]), sr);
            }
            CPC;
        }
        // P @ V: A-fragments built directly from C-fragments (layout identity)
        uint32_t* Vh = Vst + (kt & 1) * 9216;
        uint32_t* Vl = Vh + 4608;
#pragma unroll
        for (int ks = 0; ks < 4; ks++) {
            int cb = ks * 8;
            uint32_t ah0, ah1, ah2, ah3, al0, al1, al2, al3;
            h2split(c[2 * ks][0], c[2 * ks][1], ah0, al0);
            h2split(c[2 * ks][2], c[2 * ks][3], ah1, al1);
            h2split(c[2 * ks + 1][0], c[2 * ks + 1][1], ah2, al2);
            h2split(c[2 * ks + 1][2], c[2 * ks + 1][3], ah3, al3);
#pragma unroll
            for (int nb2 = 0; nb2 < 8; nb2++) {
                uint32_t bh0, bh1, bh2, bh3, bl0, bl1, bl2, bl3;
                uint32_t bd = sptr(&Vh[(nb2 * 16 + brow) * VST2 + cb + bcolb]);
                LDSM4(bh0, bh1, bh2, bh3, bd);
                bd = sptr(&Vl[(nb2 * 16 + brow) * VST2 + cb + bcolb]);
                LDSM4(bl0, bl1, bl2, bl3, bd);
                MMAH(o[2 * nb2], ah0, ah1, ah2, ah3, bh0, bh1);
                MMAH(o[2 * nb2], ah0, ah1, ah2, ah3, bl0, bl1);
                MMAH(o[2 * nb2], al0, al1, al2, al3, bh0, bh1);
                MMAH(o[2 * nb2 + 1], ah0, ah1, ah2, ah3, bh2, bh3);
                MMAH(o[2 * nb2 + 1], ah0, ah1, ah2, ah3, bl2, bl3);
                MMAH(o[2 * nb2 + 1], al0, al1, al2, al3, bh2, bh3);
            }
        }
    }
    float inv_lo = 1.f / l_lo, inv_hi = 1.f / l_hi;
    float* d_lo = g_ctx + ((size_t)(b * SEQ + q0 + r_lo)) * HID + h * HD;
    float* d_hi = g_ctx + ((size_t)(b * SEQ + q0 + r_hi)) * HID + h * HD;
#pragma unroll
    for (int nb = 0; nb < 16; nb++) {
        *(float2*)&d_lo[nb * 8 + 2 * gc] = make_float2(o[nb][0] * inv_lo, o[nb][1] * inv_lo);
        *(float2*)&d_hi[nb * 8 + 2 * gc] = make_float2(o[nb][2] * inv_hi, o[nb][3] * inv_hi);
    }
}

extern "C" void kernel_launch(void* const* d_in, const int* in_sizes, int n_in,
                              void* d_out, int out_size) {
    const float* x = (const float*)d_in[0];
    const float* wq = (const float*)d_in[1];
    const float* wk = (const float*)d_in[2];
    const float* wv = (const float*)d_in[3];
    const float* wo = (const float*)d_in[4];
    float* out = (float*)d_out;
    cudaFuncSetAttribute(k_attn, cudaFuncAttributeMaxDynamicSharedMemorySize, ATTN_SMEM);
    cudaFuncSetAttribute(k_gemm, cudaFuncAttributeMaxDynamicSharedMemorySize, GEMM_SMEM);
    k_tab<<<256, 512>>>();
    k_wabs_partial<<<dim3(64, 4), 256>>>(wq, wk, wv, wo);
    k_wabs_final<<<4, 64>>>();
    k_quant_w<<<dim3(HID * HID / 1024, 4), 256>>>(wq, wk, wv, wo);
    k_quant_act<<<TOK, 256>>>(x, 0);
    k_gemm<<<dim3(16, 32, 3), 256, GEMM_SMEM>>>(-1, out);
    k_attn<<<dim3(NH, 2, SEQ / 128), 256, ATTN_SMEM>>>();
    k_quant_act<<<TOK, 256>>>(nullptr, 1);
    k_gemm<<<dim3(16, 32), 256, GEMM_SMEM>>>(3, out);
}